// round 1
// baseline (speedup 1.0000x reference)
#include <cuda_runtime.h>

// Problem constants (hardcoded per reference): B=4, C=T=16, n=1024, KS=3
// x        [4,16,1024,16]  f32
// att_beta [1,1,1024,1024] f32
// theta    [48,16]         f32
// bias     [16]            f32
// Lk       [1024,3072]     f32  (first 1024 cols are exactly identity)
// out      [4,16,1024,16]  f32 = softmax_ch( cos_att * relu(x_gc_t + x) )

// ---------------- scratch (device globals; no runtime allocation) -------------
__device__ float g_XM[1024 * 2048];            // XM for s=1,2 blocks: [r=1024][2048]
__device__ float g_gc[4 * 1024 * 16 * 16];     // x_gc_t in [b][i][t][ch] layout
__device__ float g_cos[4 * 1024 * 16 * 16];    // cos attention in [b][i][t][ch] layout

// =============================================================================
// K1: XM[r, j] = sum_k x_tmp[r,k] * Lk[k, 1024 + j],  r<1024, j<2048, k<1024
//     x_tmp[r,k] = x[(r>>4)*16384 + k*16 + (r&15)]
// Classic 128x128x16 SGEMM, 256 threads, 8x8 per thread.
// =============================================================================
__global__ __launch_bounds__(256) void k1_gemm(const float* __restrict__ x,
                                               const float* __restrict__ Lk)
{
    __shared__ float As[16][132];
    __shared__ float Bs[16][132];
    const int tid = threadIdx.x;
    const int tx = tid & 15, ty = tid >> 4;
    const int row0 = blockIdx.y * 128;
    const int col0 = blockIdx.x * 128;

    float acc[8][8];
#pragma unroll
    for (int i = 0; i < 8; i++)
#pragma unroll
        for (int j = 0; j < 8; j++) acc[i][j] = 0.f;

    for (int k0 = 0; k0 < 1024; k0 += 16) {
#pragma unroll
        for (int it = 0; it < 8; ++it) {
            int li = tid + it * 256;
            int m = li & 127, kk = li >> 7;
            int r = row0 + m;
            As[kk][m] = x[((r >> 4) << 14) + ((k0 + kk) << 4) + (r & 15)];
        }
#pragma unroll
        for (int it = 0; it < 8; ++it) {
            int li = tid + it * 256;
            int j = li & 127, kk = li >> 7;
            Bs[kk][j] = Lk[(k0 + kk) * 3072 + 1024 + col0 + j];
        }
        __syncthreads();
#pragma unroll
        for (int kk = 0; kk < 16; ++kk) {
            float ra[8], rb[8];
            *(float4*)(ra)     = *(const float4*)(&As[kk][ty * 8]);
            *(float4*)(ra + 4) = *(const float4*)(&As[kk][ty * 8 + 4]);
            *(float4*)(rb)     = *(const float4*)(&Bs[kk][tx * 8]);
            *(float4*)(rb + 4) = *(const float4*)(&Bs[kk][tx * 8 + 4]);
#pragma unroll
            for (int i = 0; i < 8; i++)
#pragma unroll
                for (int j = 0; j < 8; j++)
                    acc[i][j] = fmaf(ra[i], rb[j], acc[i][j]);
        }
        __syncthreads();
    }
#pragma unroll
    for (int i = 0; i < 8; i++) {
        float* dst = g_XM + (row0 + ty * 8 + i) * 2048 + col0 + tx * 8;
        *(float4*)(dst)     = *(float4*)(&acc[i][0]);
        *(float4*)(dst + 4) = *(float4*)(&acc[i][4]);
    }
}

// =============================================================================
// K2: g_gc[b][i][tau][ch] = bias[ch]
//     + sum_{t'} ( x[b,tau,i,t']*theta[3t',ch]             (s=0 block == I)
//                + XM[r, i]      *theta[3t'+1,ch]
//                + XM[r, 1024+i] *theta[3t'+2,ch] ),  r = b*256 + tau*16 + t'
// One thread per (b,tau,i), i fastest for coalesced XM reads.
// =============================================================================
__global__ __launch_bounds__(256) void k2_fold(const float* __restrict__ x,
                                               const float* __restrict__ theta,
                                               const float* __restrict__ bias)
{
    __shared__ float th[768];
    __shared__ float bs[16];
    const int tid = threadIdx.x;
    for (int q = tid; q < 768; q += 256) th[q] = theta[q];
    if (tid < 16) bs[tid] = bias[tid];
    __syncthreads();

    const int idx = blockIdx.x * 256 + tid;   // b*16384 + tau*1024 + i
    const int i   = idx & 1023;
    const int tau = (idx >> 10) & 15;
    const int b   = idx >> 14;

    const float* xr = x + (((b << 4) + tau) << 14) + (i << 4);
    float xrow[16];
#pragma unroll
    for (int q = 0; q < 4; q++)
        *(float4*)(xrow + 4 * q) = *(const float4*)(xr + 4 * q);

    float acc[16];
#pragma unroll
    for (int c = 0; c < 16; c++) acc[c] = bs[c];

    const int rbase = (b << 8) + (tau << 4);
#pragma unroll 4
    for (int tp = 0; tp < 16; ++tp) {
        const float* xm = g_XM + (rbase + tp) * 2048 + i;
        float a0 = xrow[tp];
        float a1 = xm[0];
        float a2 = xm[1024];
        const float* t0 = th + tp * 48;
#pragma unroll
        for (int c = 0; c < 16; c++)
            acc[c] += a0 * t0[c] + a1 * t0[16 + c] + a2 * t0[32 + c];
    }

    float* dst = g_gc + ((size_t)b << 18) + (i << 8) + (tau << 4);
#pragma unroll
    for (int q = 0; q < 4; q++)
        *(float4*)(dst + 4 * q) = *(float4*)(acc + 4 * q);
}

// =============================================================================
// K3: cosine attention per (b,c):
//   acc_i[t] = sum_j sigmoid(beta[i,j] * dot(x_i,x_j)/(n_i*n_j + 1e-7)) * x_j[t]
// grid (4 i-tiles of 256, 64 bc). j staged in 8KB smem tiles of 128 rows.
// =============================================================================
__global__ __launch_bounds__(256) void k3_att(const float* __restrict__ x,
                                              const float* __restrict__ beta)
{
    __shared__ float xjs[128 * 16];  // 8 KB tile of x_bc rows
    __shared__ float njs[128];

    const int bc = blockIdx.y;
    const float* xbc = x + bc * 16384;
    const int i = blockIdx.x * 256 + threadIdx.x;

    float xi[16];
#pragma unroll
    for (int q = 0; q < 4; q++)
        *(float4*)(xi + 4 * q) = *(const float4*)(xbc + i * 16 + 4 * q);
    float s2 = 0.f;
#pragma unroll
    for (int t = 0; t < 16; t++) s2 = fmaf(xi[t], xi[t], s2);
    const float ni = sqrtf(s2);

    float acc[16];
#pragma unroll
    for (int t = 0; t < 16; t++) acc[t] = 0.f;

    const float* brow = beta + i * 1024;

    for (int j0 = 0; j0 < 1024; j0 += 128) {
        __syncthreads();
        // stage 128 rows of x_bc (2048 floats = 512 float4 over 256 threads)
        for (int q = threadIdx.x; q < 512; q += 256)
            ((float4*)xjs)[q] = ((const float4*)(xbc + j0 * 16))[q];
        __syncthreads();
        if (threadIdx.x < 128) {
            float s = 0.f;
#pragma unroll
            for (int t = 0; t < 16; t++) {
                float v = xjs[threadIdx.x * 16 + t];
                s = fmaf(v, v, s);
            }
            njs[threadIdx.x] = sqrtf(s);
        }
        __syncthreads();

#pragma unroll 2
        for (int jj = 0; jj < 128; jj += 4) {
            float4 b4 = *(const float4*)(brow + j0 + jj);
            const float bv[4] = {b4.x, b4.y, b4.z, b4.w};
#pragma unroll
            for (int u = 0; u < 4; u++) {
                const int j = jj + u;
                float4 xa = *(const float4*)(xjs + j * 16);
                float4 xb = *(const float4*)(xjs + j * 16 + 4);
                float4 xc = *(const float4*)(xjs + j * 16 + 8);
                float4 xd = *(const float4*)(xjs + j * 16 + 12);
                // 4-way partial dot for ILP
                float d0 = xi[0] * xa.x + xi[1] * xa.y + xi[2] * xa.z + xi[3] * xa.w;
                float d1 = xi[4] * xb.x + xi[5] * xb.y + xi[6] * xb.z + xi[7] * xb.w;
                float d2 = xi[8] * xc.x + xi[9] * xc.y + xi[10] * xc.z + xi[11] * xc.w;
                float d3 = xi[12] * xd.x + xi[13] * xd.y + xi[14] * xd.z + xi[15] * xd.w;
                float dot = (d0 + d1) + (d2 + d3);
                float denom = fmaf(ni, njs[j], 1e-7f);
                float cosv = __fdividef(dot, denom);
                float z = bv[u] * cosv;
                float p = __fdividef(1.f, 1.f + __expf(-z));
                acc[0]  = fmaf(p, xa.x, acc[0]);
                acc[1]  = fmaf(p, xa.y, acc[1]);
                acc[2]  = fmaf(p, xa.z, acc[2]);
                acc[3]  = fmaf(p, xa.w, acc[3]);
                acc[4]  = fmaf(p, xb.x, acc[4]);
                acc[5]  = fmaf(p, xb.y, acc[5]);
                acc[6]  = fmaf(p, xb.z, acc[6]);
                acc[7]  = fmaf(p, xb.w, acc[7]);
                acc[8]  = fmaf(p, xc.x, acc[8]);
                acc[9]  = fmaf(p, xc.y, acc[9]);
                acc[10] = fmaf(p, xc.z, acc[10]);
                acc[11] = fmaf(p, xc.w, acc[11]);
                acc[12] = fmaf(p, xd.x, acc[12]);
                acc[13] = fmaf(p, xd.y, acc[13]);
                acc[14] = fmaf(p, xd.z, acc[14]);
                acc[15] = fmaf(p, xd.w, acc[15]);
            }
        }
    }

    // g_cos[b][i][t][ch], b = bc>>4, ch = bc&15
    const int b = bc >> 4, ch = bc & 15;
    float* dst = g_cos + ((((size_t)(b << 10) + i) << 8)) + ch;
#pragma unroll
    for (int t = 0; t < 16; t++) dst[t << 4] = acc[t];
}

// =============================================================================
// K4: out[b,ch,i,t] = softmax_ch( g_cos * relu(g_gc + x) )
// One thread per (b,i,t).
// =============================================================================
__global__ __launch_bounds__(256) void k4_final(const float* __restrict__ x,
                                                float* __restrict__ out)
{
    const int idx = blockIdx.x * 256 + threadIdx.x;  // ((b*1024+i)*16+t)
    const int t = idx & 15;
    const int i = (idx >> 4) & 1023;
    const int b = idx >> 14;

    const float* gc = g_gc + (size_t)idx * 16;
    const float* cs = g_cos + (size_t)idx * 16;

    float g[16];
#pragma unroll
    for (int c = 0; c < 16; c++) {
        float xv = x[(((b << 4) + c) << 14) + (i << 4) + t];
        float r = gc[c] + xv;
        r = r > 0.f ? r : 0.f;
        g[c] = cs[c] * r;
    }
    float m = g[0];
#pragma unroll
    for (int c = 1; c < 16; c++) m = fmaxf(m, g[c]);
    float s = 0.f;
#pragma unroll
    for (int c = 0; c < 16; c++) {
        float e = __expf(g[c] - m);
        g[c] = e;
        s += e;
    }
    float rs = __fdividef(1.f, s);
#pragma unroll
    for (int c = 0; c < 16; c++)
        out[(((b << 4) + c) << 14) + (i << 4) + t] = g[c] * rs;
}

// =============================================================================
extern "C" void kernel_launch(void* const* d_in, const int* in_sizes, int n_in,
                              void* d_out, int out_size)
{
    const float* x     = (const float*)d_in[0];  // [4,16,1024,16]
    const float* beta  = (const float*)d_in[1];  // [1,1,1024,1024]
    const float* theta = (const float*)d_in[2];  // [48,16]
    const float* bias  = (const float*)d_in[3];  // [16]
    const float* Lk    = (const float*)d_in[4];  // [1024,3072]
    float* out = (float*)d_out;

    k1_gemm<<<dim3(16, 8), 256>>>(x, Lk);
    k2_fold<<<256, 256>>>(x, theta, bias);
    k3_att<<<dim3(4, 64), 256>>>(x, beta);
    k4_final<<<256, 256>>>(x, out);
}

// round 3
// speedup vs baseline: 1.1755x; 1.1755x over previous
#include <cuda_runtime.h>
#include <cuda_bf16.h>
#include <cstdint>

// Problem constants: B=4, C=T=16, n=1024, KS=3
// x        [4,16,1024,16]  f32
// att_beta [1,1,1024,1024] f32
// theta    [48,16]         f32
// bias     [16]            f32
// Lk       [1024,3072]     f32  (first 1024 cols exactly identity)
// out = softmax_ch( cos_att * relu(x_gc_t + x) )

// ---------------- scratch (device globals) ----------------------------------
__device__ float g_XM[1024 * 2048];                        // GEMM result
__device__ float g_gc[4 * 1024 * 16 * 16];                 // [b][i][t][ch]
__device__ float g_cos[4 * 1024 * 16 * 16];                // [b][i][t][ch]
__device__ __align__(16) __nv_bfloat16 g_Ahi[1024 * 1024]; // x_tmp hi, K-major
__device__ __align__(16) __nv_bfloat16 g_Alo[1024 * 1024];
__device__ __align__(16) __nv_bfloat16 g_Bhi[2048 * 1024]; // Lk2^T hi, K-major
__device__ __align__(16) __nv_bfloat16 g_Blo[2048 * 1024];

// ---------------- helpers ----------------------------------------------------
__device__ __forceinline__ uint32_t smem_u32(const void* p) {
    uint32_t a;
    asm("{ .reg .u64 t; cvta.to.shared.u64 t, %1; cvt.u32.u64 %0, t; }"
        : "=r"(a) : "l"(p));
    return a;
}
__device__ __forceinline__ void cp_async16(uint32_t dst, const void* src) {
    asm volatile("cp.async.cg.shared.global [%0], [%1], 16;" :: "r"(dst), "l"(src));
}
__device__ __forceinline__ void cp_commit() {
    asm volatile("cp.async.commit_group;" ::: "memory");
}
template <int N> __device__ __forceinline__ void cp_wait() {
    asm volatile("cp.async.wait_group %0;" :: "n"(N) : "memory");
}
__device__ __forceinline__ void mma16816(float* d, const uint32_t* a,
                                         const uint32_t* b) {
    asm volatile(
        "mma.sync.aligned.m16n8k16.row.col.f32.bf16.bf16.f32 "
        "{%0,%1,%2,%3}, {%4,%5,%6,%7}, {%8,%9}, {%0,%1,%2,%3};\n"
        : "+f"(d[0]), "+f"(d[1]), "+f"(d[2]), "+f"(d[3])
        : "r"(a[0]), "r"(a[1]), "r"(a[2]), "r"(a[3]), "r"(b[0]), "r"(b[1]));
}

// =============================================================================
// P1: x -> A_hi/A_lo.  A[r][k] = x[(r>>4)*16384 + k*16 + (r&15)], r,k < 1024
// =============================================================================
__global__ __launch_bounds__(256) void p1_convA(const float* __restrict__ x)
{
    __shared__ float s[16][258];
    const int g = blockIdx.x;          // 0..63 = b*16+c
    const int tid = threadIdx.x;
    for (int c = 0; c < 4; c++) {
        __syncthreads();
#pragma unroll
        for (int it = 0; it < 16; it++) {
            int idx = tid + it * 256;                 // 0..4095
            float v = x[g * 16384 + c * 4096 + idx];
            s[idx & 15][idx >> 4] = v;
        }
        __syncthreads();
        const int rl = tid >> 4;
        const int kk0 = (tid & 15) * 16;
        alignas(16) __nv_bfloat16 hb[16], lb[16];
#pragma unroll
        for (int q = 0; q < 16; q++) {
            float v = s[rl][kk0 + q];
            __nv_bfloat16 h = __float2bfloat16(v);
            hb[q] = h;
            lb[q] = __float2bfloat16(v - __bfloat162float(h));
        }
        size_t off = (size_t)(g * 16 + rl) * 1024 + c * 256 + kk0;
        *(uint4*)(g_Ahi + off)     = *(uint4*)(hb);
        *(uint4*)(g_Ahi + off + 8) = *(uint4*)(hb + 8);
        *(uint4*)(g_Alo + off)     = *(uint4*)(lb);
        *(uint4*)(g_Alo + off + 8) = *(uint4*)(lb + 8);
    }
}

// =============================================================================
// P2: Lk2 transpose -> B_hi/B_lo.  Bt[j][k] = Lk[k*3072 + 1024 + j]
// =============================================================================
__global__ __launch_bounds__(256) void p2_convB(const float* __restrict__ Lk)
{
    __shared__ float s[32][33];
    const int jt = blockIdx.x;   // 0..63
    const int kt = blockIdx.y;   // 0..31
    const int tx = threadIdx.x & 31, ty = threadIdx.x >> 5;
#pragma unroll
    for (int p = 0; p < 4; p++) {
        int ky = ty + p * 8;
        s[tx][ky] = Lk[(kt * 32 + ky) * 3072 + 1024 + jt * 32 + tx];
    }
    __syncthreads();
#pragma unroll
    for (int p = 0; p < 4; p++) {
        int jy = ty + p * 8;
        float v = s[jy][tx];
        __nv_bfloat16 h = __float2bfloat16(v);
        size_t off = (size_t)(jt * 32 + jy) * 1024 + kt * 32 + tx;
        g_Bhi[off] = h;
        g_Blo[off] = __float2bfloat16(v - __bfloat162float(h));
    }
}

// =============================================================================
// K1: split-bf16 HMMA GEMM via mma.sync m16n8k16.
// D[128x128] per CTA; grid (16 coltiles, 8 rowtiles), 256 threads (8 warps).
// Warp tile 32(m) x 64(n). K staged in 64 chunks of 16, double-buffered
// cp.async. 3 passes: Ahi*Bhi + Ahi*Blo + Alo*Bhi into same accumulators.
// smem rows are 32B with 16B-chunk XOR swizzle -> fragment LDS conflict-free.
// =============================================================================
__global__ __launch_bounds__(256) void k1_mma()
{
    // [stage][array: 0=Ahi 1=Alo 2=Bhi 3=Blo][128 rows * 32 bytes]
    __shared__ __align__(16) uint8_t smem[2][4][4096];

    const int tid = threadIdx.x;
    const int wid = tid >> 5, lane = tid & 31;
    const int g = lane >> 2, tg = lane & 3;
    const int wm = (wid & 3) * 32;       // warp m offset within CTA tile
    const int wn = (wid >> 2) * 64;      // warp n offset within CTA tile
    const int row0 = blockIdx.y * 128;
    const int col0 = blockIdx.x * 128;

    const __nv_bfloat16* gsrc[4] = {
        g_Ahi + (size_t)row0 * 1024, g_Alo + (size_t)row0 * 1024,
        g_Bhi + (size_t)col0 * 1024, g_Blo + (size_t)col0 * 1024};

    float acc[2][8][4];
#pragma unroll
    for (int mt = 0; mt < 2; mt++)
#pragma unroll
        for (int nt = 0; nt < 8; nt++)
#pragma unroll
            for (int q = 0; q < 4; q++) acc[mt][nt][q] = 0.f;

    auto load_stage = [&](int s, int kt) {
#pragma unroll
        for (int q = 0; q < 4; q++) {
            int idx = tid + q * 256;          // 0..1023
            int arr = idx >> 8;
            int rc  = idx & 255;
            int r   = rc >> 1;                // row 0..127
            int c   = rc & 1;                 // 16B chunk 0..1
            const void* src = gsrc[arr] + (size_t)r * 1024 + kt * 16 + c * 8;
            uint32_t dst = smem_u32(&smem[s][arr][0]) + r * 32 +
                           ((c * 16) ^ (((r >> 2) & 1) << 4));
            cp_async16(dst, src);
        }
        cp_commit();
    };

    // swizzled 32-bit fragment load: word w (0..7) of row r
    auto lds = [&](const uint8_t* base, int r, int w) -> uint32_t {
        return *(const uint32_t*)(base + r * 32 +
                                  ((w * 4) ^ (((r >> 2) & 1) << 4)));
    };

    load_stage(0, 0);

    for (int kt = 0; kt < 64; kt++) {
        if (kt + 1 < 64) load_stage((kt + 1) & 1, kt + 1);
        if (kt + 1 < 64) cp_wait<1>(); else cp_wait<0>();
        __syncthreads();

        const uint8_t* Ahi = smem[kt & 1][0];
        const uint8_t* Alo = smem[kt & 1][1];
        const uint8_t* Bhi = smem[kt & 1][2];
        const uint8_t* Blo = smem[kt & 1][3];

#pragma unroll
        for (int pass = 0; pass < 3; pass++) {
            const uint8_t* Ab = (pass == 2) ? Alo : Ahi;
            const uint8_t* Bb = (pass == 1) ? Blo : Bhi;

            uint32_t afr[2][4];
#pragma unroll
            for (int mt = 0; mt < 2; mt++) {
                int r = wm + mt * 16 + g;
                afr[mt][0] = lds(Ab, r,     tg);
                afr[mt][1] = lds(Ab, r + 8, tg);
                afr[mt][2] = lds(Ab, r,     tg + 4);
                afr[mt][3] = lds(Ab, r + 8, tg + 4);
            }
            uint32_t bfr[8][2];
#pragma unroll
            for (int nt = 0; nt < 8; nt++) {
                int n = wn + nt * 8 + g;
                bfr[nt][0] = lds(Bb, n, tg);
                bfr[nt][1] = lds(Bb, n, tg + 4);
            }
#pragma unroll
            for (int mt = 0; mt < 2; mt++)
#pragma unroll
                for (int nt = 0; nt < 8; nt++)
                    mma16816(acc[mt][nt], afr[mt], bfr[nt]);
        }
        __syncthreads();
    }

    // epilogue: d0,d1 -> (row, col..col+1); d2,d3 -> (row+8, ...)
#pragma unroll
    for (int mt = 0; mt < 2; mt++) {
#pragma unroll
        for (int nt = 0; nt < 8; nt++) {
            int r = row0 + wm + mt * 16 + g;
            int c = col0 + wn + nt * 8 + tg * 2;
            float2 v01 = make_float2(acc[mt][nt][0], acc[mt][nt][1]);
            float2 v23 = make_float2(acc[mt][nt][2], acc[mt][nt][3]);
            *(float2*)&g_XM[(size_t)r * 2048 + c]       = v01;
            *(float2*)&g_XM[(size_t)(r + 8) * 2048 + c] = v23;
        }
    }
}

// =============================================================================
// K2: fold theta
// =============================================================================
__global__ __launch_bounds__(256) void k2_fold(const float* __restrict__ x,
                                               const float* __restrict__ theta,
                                               const float* __restrict__ bias)
{
    __shared__ float th[768];
    __shared__ float bs[16];
    const int tid = threadIdx.x;
    for (int q = tid; q < 768; q += 256) th[q] = theta[q];
    if (tid < 16) bs[tid] = bias[tid];
    __syncthreads();

    const int idx = blockIdx.x * 256 + tid;
    const int i   = idx & 1023;
    const int tau = (idx >> 10) & 15;
    const int b   = idx >> 14;

    const float* xr = x + (((b << 4) + tau) << 14) + (i << 4);
    float xrow[16];
#pragma unroll
    for (int q = 0; q < 4; q++)
        *(float4*)(xrow + 4 * q) = *(const float4*)(xr + 4 * q);

    float acc[16];
#pragma unroll
    for (int c = 0; c < 16; c++) acc[c] = bs[c];

    const int rbase = (b << 8) + (tau << 4);
#pragma unroll 4
    for (int tp = 0; tp < 16; ++tp) {
        const float* xm = g_XM + (size_t)(rbase + tp) * 2048 + i;
        float a0 = xrow[tp];
        float a1 = xm[0];
        float a2 = xm[1024];
        const float* t0 = th + tp * 48;
#pragma unroll
        for (int c = 0; c < 16; c++)
            acc[c] += a0 * t0[c] + a1 * t0[16 + c] + a2 * t0[32 + c];
    }

    float* dst = g_gc + ((size_t)b << 18) + (i << 8) + (tau << 4);
#pragma unroll
    for (int q = 0; q < 4; q++)
        *(float4*)(dst + 4 * q) = *(float4*)(acc + 4 * q);
}

// =============================================================================
// K3: cosine attention (rsqrt inverse norms)
// =============================================================================
__global__ __launch_bounds__(256) void k3_att(const float* __restrict__ x,
                                              const float* __restrict__ beta)
{
    __shared__ float xjs[128 * 16];
    __shared__ float injs[128];

    const int bc = blockIdx.y;
    const float* xbc = x + bc * 16384;
    const int i = blockIdx.x * 256 + threadIdx.x;

    float xi[16];
#pragma unroll
    for (int q = 0; q < 4; q++)
        *(float4*)(xi + 4 * q) = *(const float4*)(xbc + i * 16 + 4 * q);
    float s2 = 0.f;
#pragma unroll
    for (int t = 0; t < 16; t++) s2 = fmaf(xi[t], xi[t], s2);
    const float inv_ni = rsqrtf(s2);

    float acc[16];
#pragma unroll
    for (int t = 0; t < 16; t++) acc[t] = 0.f;

    const float* brow = beta + (size_t)i * 1024;

    for (int j0 = 0; j0 < 1024; j0 += 128) {
        __syncthreads();
        for (int q = threadIdx.x; q < 512; q += 256)
            ((float4*)xjs)[q] = ((const float4*)(xbc + j0 * 16))[q];
        __syncthreads();
        if (threadIdx.x < 128) {
            float s = 0.f;
#pragma unroll
            for (int t = 0; t < 16; t++) {
                float v = xjs[threadIdx.x * 16 + t];
                s = fmaf(v, v, s);
            }
            injs[threadIdx.x] = rsqrtf(s);
        }
        __syncthreads();

#pragma unroll 2
        for (int jj = 0; jj < 128; jj += 4) {
            float4 b4 = *(const float4*)(brow + j0 + jj);
            const float bv[4] = {b4.x, b4.y, b4.z, b4.w};
#pragma unroll
            for (int u = 0; u < 4; u++) {
                const int j = jj + u;
                float4 xa = *(const float4*)(xjs + j * 16);
                float4 xb = *(const float4*)(xjs + j * 16 + 4);
                float4 xc = *(const float4*)(xjs + j * 16 + 8);
                float4 xd = *(const float4*)(xjs + j * 16 + 12);
                float d0 = xi[0] * xa.x + xi[1] * xa.y + xi[2] * xa.z + xi[3] * xa.w;
                float d1 = xi[4] * xb.x + xi[5] * xb.y + xi[6] * xb.z + xi[7] * xb.w;
                float d2 = xi[8] * xc.x + xi[9] * xc.y + xi[10] * xc.z + xi[11] * xc.w;
                float d3 = xi[12] * xd.x + xi[13] * xd.y + xi[14] * xd.z + xi[15] * xd.w;
                float dot = (d0 + d1) + (d2 + d3);
                float z = bv[u] * dot * (inv_ni * injs[j]);
                float p = __fdividef(1.f, 1.f + __expf(-z));
                acc[0]  = fmaf(p, xa.x, acc[0]);
                acc[1]  = fmaf(p, xa.y, acc[1]);
                acc[2]  = fmaf(p, xa.z, acc[2]);
                acc[3]  = fmaf(p, xa.w, acc[3]);
                acc[4]  = fmaf(p, xb.x, acc[4]);
                acc[5]  = fmaf(p, xb.y, acc[5]);
                acc[6]  = fmaf(p, xb.z, acc[6]);
                acc[7]  = fmaf(p, xb.w, acc[7]);
                acc[8]  = fmaf(p, xc.x, acc[8]);
                acc[9]  = fmaf(p, xc.y, acc[9]);
                acc[10] = fmaf(p, xc.z, acc[10]);
                acc[11] = fmaf(p, xc.w, acc[11]);
                acc[12] = fmaf(p, xd.x, acc[12]);
                acc[13] = fmaf(p, xd.y, acc[13]);
                acc[14] = fmaf(p, xd.z, acc[14]);
                acc[15] = fmaf(p, xd.w, acc[15]);
            }
        }
    }

    const int b = bc >> 4, ch = bc & 15;
    float* dst = g_cos + ((((size_t)(b << 10) + i) << 8)) + ch;
#pragma unroll
    for (int t = 0; t < 16; t++) dst[t << 4] = acc[t];
}

// =============================================================================
// K4: fuse + channel softmax
// =============================================================================
__global__ __launch_bounds__(256) void k4_final(const float* __restrict__ x,
                                                float* __restrict__ out)
{
    const int idx = blockIdx.x * 256 + threadIdx.x;
    const int t = idx & 15;
    const int i = (idx >> 4) & 1023;
    const int b = idx >> 14;

    const float* gc = g_gc + (size_t)idx * 16;
    const float* cs = g_cos + (size_t)idx * 16;

    float g[16];
#pragma unroll
    for (int c = 0; c < 16; c++) {
        float xv = x[(((b << 4) + c) << 14) + (i << 4) + t];
        float r = gc[c] + xv;
        r = r > 0.f ? r : 0.f;
        g[c] = cs[c] * r;
    }
    float m = g[0];
#pragma unroll
    for (int c = 1; c < 16; c++) m = fmaxf(m, g[c]);
    float s = 0.f;
#pragma unroll
    for (int c = 0; c < 16; c++) {
        float e = __expf(g[c] - m);
        g[c] = e;
        s += e;
    }
    float rs = __fdividef(1.f, s);
#pragma unroll
    for (int c = 0; c < 16; c++)
        out[(((b << 4) + c) << 14) + (i << 4) + t] = g[c] * rs;
}

// =============================================================================
extern "C" void kernel_launch(void* const* d_in, const int* in_sizes, int n_in,
                              void* d_out, int out_size)
{
    const float* x     = (const float*)d_in[0];
    const float* beta  = (const float*)d_in[1];
    const float* theta = (const float*)d_in[2];
    const float* bias  = (const float*)d_in[3];
    const float* Lk    = (const float*)d_in[4];
    float* out = (float*)d_out;

    p1_convA<<<64, 256>>>(x);
    p2_convB<<<dim3(64, 32), 256>>>(Lk);
    k1_mma<<<dim3(16, 8), 256>>>();
    k3_att<<<dim3(4, 64), 256>>>(x, beta);
    k2_fold<<<256, 256>>>(x, theta, bias);
    k4_final<<<256, 256>>>(x, out);
}

// round 4
// speedup vs baseline: 1.7953x; 1.5273x over previous
#include <cuda_runtime.h>
#include <cuda_bf16.h>
#include <cstdint>

// Problem constants: B=4, C=T=16, n=1024, KS=3
// out = softmax_ch( cos_att * relu(x_gc_t + x) )

// ---------------- scratch (device globals) ----------------------------------
__device__ float g_XM[1024 * 2048];                        // GEMM result
__device__ float g_gc[4 * 1024 * 16 * 16];                 // [b][i][t][ch]
__device__ float g_cos[4 * 1024 * 16 * 16];                // [b][i][t][ch]
__device__ __align__(16) __nv_bfloat16 g_Ahi[1024 * 1024]; // x_tmp hi, K-major
__device__ __align__(16) __nv_bfloat16 g_Alo[1024 * 1024];
__device__ __align__(16) __nv_bfloat16 g_Bhi[2048 * 1024]; // Lk2^T hi, K-major
__device__ __align__(16) __nv_bfloat16 g_Blo[2048 * 1024];
__device__ __align__(16) __nv_bfloat16 g_Xbfh[64 * 1024 * 16]; // x[bc][i][t] hi
__device__ __align__(16) __nv_bfloat16 g_Xbfl[64 * 1024 * 16]; // lo
__device__ __align__(16) __nv_bfloat16 g_XTh[64 * 16 * 1024];  // x[bc][t][i] hi
__device__ __align__(16) __nv_bfloat16 g_XTl[64 * 16 * 1024];  // lo
__device__ float g_inorm[64 * 1024];                           // 1/||x_i||

// ---------------- helpers ----------------------------------------------------
__device__ __forceinline__ uint32_t smem_u32(const void* p) {
    uint32_t a;
    asm("{ .reg .u64 t; cvta.to.shared.u64 t, %1; cvt.u32.u64 %0, t; }"
        : "=r"(a) : "l"(p));
    return a;
}
__device__ __forceinline__ void cp_async16(uint32_t dst, const void* src) {
    asm volatile("cp.async.cg.shared.global [%0], [%1], 16;" :: "r"(dst), "l"(src));
}
__device__ __forceinline__ void cp_commit() {
    asm volatile("cp.async.commit_group;" ::: "memory");
}
template <int N> __device__ __forceinline__ void cp_wait() {
    asm volatile("cp.async.wait_group %0;" :: "n"(N) : "memory");
}
__device__ __forceinline__ void mma16816(float* d, const uint32_t* a,
                                         const uint32_t* b) {
    asm volatile(
        "mma.sync.aligned.m16n8k16.row.col.f32.bf16.bf16.f32 "
        "{%0,%1,%2,%3}, {%4,%5,%6,%7}, {%8,%9}, {%0,%1,%2,%3};\n"
        : "+f"(d[0]), "+f"(d[1]), "+f"(d[2]), "+f"(d[3])
        : "r"(a[0]), "r"(a[1]), "r"(a[2]), "r"(a[3]), "r"(b[0]), "r"(b[1]));
}
__device__ __forceinline__ uint32_t pack_bf16x2(float hi, float lo) {
    uint32_t r;
    asm("cvt.rn.satfinite.bf16x2.f32 %0, %1, %2;" : "=r"(r) : "f"(hi), "f"(lo));
    return r;
}
__device__ __forceinline__ float bf16lo_f(uint32_t u) {
    return __uint_as_float(u << 16);
}
__device__ __forceinline__ float bf16hi_f(uint32_t u) {
    return __uint_as_float(u & 0xFFFF0000u);
}

// =============================================================================
// P1: x -> (a) g_Ahi/lo  A[r][k=i], r=(bc)*16+t
//          (b) g_Xbfh/l  [bc][i][t] + g_inorm
//          (c) g_XTh/l   [bc][t][i]
// =============================================================================
__global__ __launch_bounds__(256) void p1_convA(const float* __restrict__ x)
{
    __shared__ float s[16][258];
    const int g = blockIdx.x;          // 0..63 = bc
    const int tid = threadIdx.x;
    for (int c = 0; c < 4; c++) {
        __syncthreads();
#pragma unroll
        for (int it = 0; it < 16; it++) {
            int idx = tid + it * 256;                 // i_local*16 + t
            float v = x[g * 16384 + c * 4096 + idx];
            s[idx & 15][idx >> 4] = v;
        }
        __syncthreads();
        // (a) A matrices: row = g*16 + t, cols i
        {
            const int rl = tid >> 4;
            const int kk0 = (tid & 15) * 16;
            alignas(16) __nv_bfloat16 hb[16], lb[16];
#pragma unroll
            for (int q = 0; q < 16; q++) {
                float v = s[rl][kk0 + q];
                __nv_bfloat16 h = __float2bfloat16(v);
                hb[q] = h;
                lb[q] = __float2bfloat16(v - __bfloat162float(h));
            }
            size_t off = (size_t)(g * 16 + rl) * 1024 + c * 256 + kk0;
            *(uint4*)(g_Ahi + off)     = *(uint4*)(hb);
            *(uint4*)(g_Ahi + off + 8) = *(uint4*)(hb + 8);
            *(uint4*)(g_Alo + off)     = *(uint4*)(lb);
            *(uint4*)(g_Alo + off + 8) = *(uint4*)(lb + 8);
        }
        // (b) Xbf rows [i][t] + inv norm
        {
            const int i = c * 256 + tid;
            alignas(16) __nv_bfloat16 hb[16], lb[16];
            float s2 = 0.f;
#pragma unroll
            for (int t = 0; t < 16; t++) {
                float v = s[t][tid];
                s2 = fmaf(v, v, s2);
                __nv_bfloat16 h = __float2bfloat16(v);
                hb[t] = h;
                lb[t] = __float2bfloat16(v - __bfloat162float(h));
            }
            g_inorm[g * 1024 + i] = rsqrtf(s2);
            size_t off = (size_t)(g * 1024 + i) * 16;
            *(uint4*)(g_Xbfh + off)     = *(uint4*)(hb);
            *(uint4*)(g_Xbfh + off + 8) = *(uint4*)(hb + 8);
            *(uint4*)(g_Xbfl + off)     = *(uint4*)(lb);
            *(uint4*)(g_Xbfl + off + 8) = *(uint4*)(lb + 8);
        }
        // (c) XT rows [t][i]
        {
            const int t = tid >> 4;
            const int ib = (tid & 15) * 16;
            alignas(16) __nv_bfloat16 hb[16], lb[16];
#pragma unroll
            for (int q = 0; q < 16; q++) {
                float v = s[t][ib + q];
                __nv_bfloat16 h = __float2bfloat16(v);
                hb[q] = h;
                lb[q] = __float2bfloat16(v - __bfloat162float(h));
            }
            size_t off = (size_t)(g * 16 + t) * 1024 + c * 256 + ib;
            *(uint4*)(g_XTh + off)     = *(uint4*)(hb);
            *(uint4*)(g_XTh + off + 8) = *(uint4*)(hb + 8);
            *(uint4*)(g_XTl + off)     = *(uint4*)(lb);
            *(uint4*)(g_XTl + off + 8) = *(uint4*)(lb + 8);
        }
    }
}

// =============================================================================
// P2: Lk2 transpose -> B_hi/B_lo.  Bt[j][k] = Lk[k*3072 + 1024 + j]
// =============================================================================
__global__ __launch_bounds__(256) void p2_convB(const float* __restrict__ Lk)
{
    __shared__ float s[32][33];
    const int jt = blockIdx.x;
    const int kt = blockIdx.y;
    const int tx = threadIdx.x & 31, ty = threadIdx.x >> 5;
#pragma unroll
    for (int p = 0; p < 4; p++) {
        int ky = ty + p * 8;
        s[tx][ky] = Lk[(kt * 32 + ky) * 3072 + 1024 + jt * 32 + tx];
    }
    __syncthreads();
#pragma unroll
    for (int p = 0; p < 4; p++) {
        int jy = ty + p * 8;
        float v = s[jy][tx];
        __nv_bfloat16 h = __float2bfloat16(v);
        size_t off = (size_t)(jt * 32 + jy) * 1024 + kt * 32 + tx;
        g_Bhi[off] = h;
        g_Blo[off] = __float2bfloat16(v - __bfloat162float(h));
    }
}

// =============================================================================
// K1: split-bf16 HMMA GEMM (unchanged from R3-passing version)
// =============================================================================
__global__ __launch_bounds__(256) void k1_mma()
{
    __shared__ __align__(16) uint8_t smem[2][4][4096];

    const int tid = threadIdx.x;
    const int wid = tid >> 5, lane = tid & 31;
    const int g = lane >> 2, tg = lane & 3;
    const int wm = (wid & 3) * 32;
    const int wn = (wid >> 2) * 64;
    const int row0 = blockIdx.y * 128;
    const int col0 = blockIdx.x * 128;

    const __nv_bfloat16* gsrc[4] = {
        g_Ahi + (size_t)row0 * 1024, g_Alo + (size_t)row0 * 1024,
        g_Bhi + (size_t)col0 * 1024, g_Blo + (size_t)col0 * 1024};

    float acc[2][8][4];
#pragma unroll
    for (int mt = 0; mt < 2; mt++)
#pragma unroll
        for (int nt = 0; nt < 8; nt++)
#pragma unroll
            for (int q = 0; q < 4; q++) acc[mt][nt][q] = 0.f;

    auto load_stage = [&](int s, int kt) {
#pragma unroll
        for (int q = 0; q < 4; q++) {
            int idx = tid + q * 256;
            int arr = idx >> 8;
            int rc  = idx & 255;
            int r   = rc >> 1;
            int c   = rc & 1;
            const void* src = gsrc[arr] + (size_t)r * 1024 + kt * 16 + c * 8;
            uint32_t dst = smem_u32(&smem[s][arr][0]) + r * 32 +
                           ((c * 16) ^ (((r >> 2) & 1) << 4));
            cp_async16(dst, src);
        }
        cp_commit();
    };
    auto lds = [&](const uint8_t* base, int r, int w) -> uint32_t {
        return *(const uint32_t*)(base + r * 32 +
                                  ((w * 4) ^ (((r >> 2) & 1) << 4)));
    };

    load_stage(0, 0);

    for (int kt = 0; kt < 64; kt++) {
        if (kt + 1 < 64) load_stage((kt + 1) & 1, kt + 1);
        if (kt + 1 < 64) cp_wait<1>(); else cp_wait<0>();
        __syncthreads();

        const uint8_t* Ahi = smem[kt & 1][0];
        const uint8_t* Alo = smem[kt & 1][1];
        const uint8_t* Bhi = smem[kt & 1][2];
        const uint8_t* Blo = smem[kt & 1][3];

#pragma unroll
        for (int pass = 0; pass < 3; pass++) {
            const uint8_t* Ab = (pass == 2) ? Alo : Ahi;
            const uint8_t* Bb = (pass == 1) ? Blo : Bhi;
            uint32_t afr[2][4];
#pragma unroll
            for (int mt = 0; mt < 2; mt++) {
                int r = wm + mt * 16 + g;
                afr[mt][0] = lds(Ab, r,     tg);
                afr[mt][1] = lds(Ab, r + 8, tg);
                afr[mt][2] = lds(Ab, r,     tg + 4);
                afr[mt][3] = lds(Ab, r + 8, tg + 4);
            }
            uint32_t bfr[8][2];
#pragma unroll
            for (int nt = 0; nt < 8; nt++) {
                int n = wn + nt * 8 + g;
                bfr[nt][0] = lds(Bb, n, tg);
                bfr[nt][1] = lds(Bb, n, tg + 4);
            }
#pragma unroll
            for (int mt = 0; mt < 2; mt++)
#pragma unroll
                for (int nt = 0; nt < 8; nt++)
                    mma16816(acc[mt][nt], afr[mt], bfr[nt]);
        }
        __syncthreads();
    }
#pragma unroll
    for (int mt = 0; mt < 2; mt++) {
#pragma unroll
        for (int nt = 0; nt < 8; nt++) {
            int r = row0 + wm + mt * 16 + g;
            int c = col0 + wn + nt * 8 + tg * 2;
            *(float2*)&g_XM[(size_t)r * 2048 + c] =
                make_float2(acc[mt][nt][0], acc[mt][nt][1]);
            *(float2*)&g_XM[(size_t)(r + 8) * 2048 + c] =
                make_float2(acc[mt][nt][2], acc[mt][nt][3]);
        }
    }
}

// =============================================================================
// K2: fold theta
// =============================================================================
__global__ __launch_bounds__(256) void k2_fold(const float* __restrict__ x,
                                               const float* __restrict__ theta,
                                               const float* __restrict__ bias)
{
    __shared__ float th[768];
    __shared__ float bs[16];
    const int tid = threadIdx.x;
    for (int q = tid; q < 768; q += 256) th[q] = theta[q];
    if (tid < 16) bs[tid] = bias[tid];
    __syncthreads();

    const int idx = blockIdx.x * 256 + tid;
    const int i   = idx & 1023;
    const int tau = (idx >> 10) & 15;
    const int b   = idx >> 14;

    const float* xr = x + (((b << 4) + tau) << 14) + (i << 4);
    float xrow[16];
#pragma unroll
    for (int q = 0; q < 4; q++)
        *(float4*)(xrow + 4 * q) = *(const float4*)(xr + 4 * q);

    float acc[16];
#pragma unroll
    for (int c = 0; c < 16; c++) acc[c] = bs[c];

    const int rbase = (b << 8) + (tau << 4);
#pragma unroll 4
    for (int tp = 0; tp < 16; ++tp) {
        const float* xm = g_XM + (size_t)(rbase + tp) * 2048 + i;
        float a0 = xrow[tp];
        float a1 = xm[0];
        float a2 = xm[1024];
        const float* t0 = th + tp * 48;
#pragma unroll
        for (int c = 0; c < 16; c++)
            acc[c] += a0 * t0[c] + a1 * t0[16 + c] + a2 * t0[32 + c];
    }

    float* dst = g_gc + ((size_t)b << 18) + (i << 8) + (tau << 4);
#pragma unroll
    for (int q = 0; q < 4; q++)
        *(float4*)(dst + 4 * q) = *(float4*)(acc + 4 * q);
}

// =============================================================================
// K3T: tensorized attention. grid (8 i-tiles, 64 bc), 256 thr (8 warps).
// Warp owns 16 i-rows. Per 16-j step: S = Xi·Xjᵀ (split-bf16, 3 passes,
// 2 n8 tiles), sigmoid, P repacked in-register into A-frags, O += P·X
// (split, 3 passes, 2 t-tiles). Xj / XT staged via double-buffered cp.async.
// =============================================================================
__global__ __launch_bounds__(256) void k3t(const float* __restrict__ beta)
{
    __shared__ __align__(16) uint8_t sb[2][4][4096]; // [stage][Xjh,Xjl,XTh,XTl]
    __shared__ float sInj[1024];

    const int tid  = threadIdx.x;
    const int lane = tid & 31, wid = tid >> 5;
    const int g = lane >> 2, tg = lane & 3;
    const int bc = blockIdx.y;
    const int i0 = blockIdx.x * 128;
    const int b  = bc >> 4, ch = bc & 15;

    for (int q = tid; q < 1024; q += 256) sInj[q] = g_inorm[bc * 1024 + q];

    // Xi A-fragments (k = t = 16) + inverse row norms
    const int r0 = i0 + wid * 16 + g;
    uint32_t aih[4], ail[4];
    {
        const uint32_t* Xh = (const uint32_t*)(g_Xbfh + ((size_t)bc * 1024 + r0) * 16);
        const uint32_t* Xl = (const uint32_t*)(g_Xbfl + ((size_t)bc * 1024 + r0) * 16);
        aih[0] = Xh[tg];      aih[1] = Xh[64 + tg];
        aih[2] = Xh[tg + 4];  aih[3] = Xh[64 + tg + 4];
        ail[0] = Xl[tg];      ail[1] = Xl[64 + tg];
        ail[2] = Xl[tg + 4];  ail[3] = Xl[64 + tg + 4];
    }
    const float ni0 = g_inorm[bc * 1024 + r0];
    const float ni1 = g_inorm[bc * 1024 + r0 + 8];

    float o0[4] = {0.f, 0.f, 0.f, 0.f};
    float o1[4] = {0.f, 0.f, 0.f, 0.f};

    auto stage = [&](int st, int jt) {
        const size_t xb = ((size_t)bc * 1024 + jt * 128) * 32;   // bytes
        const size_t tb = ((size_t)bc * 16384 + jt * 128) * 2;   // bytes
        const char* srcs[4] = {(const char*)g_Xbfh + xb, (const char*)g_Xbfl + xb,
                               (const char*)g_XTh + tb,  (const char*)g_XTl + tb};
#pragma unroll
        for (int a = 0; a < 4; a++) {
            int q = tid + (a & 1) * 0;   // q below
            q = tid;                      // 0..255 per array? 256 chunks, 256 thr
            uint32_t dst;
            const char* src;
            if (a < 2) { dst = (uint32_t)q * 16; src = srcs[a] + (size_t)q * 16; }
            else {
                int t = q >> 4, c = q & 15;
                dst = t * 256 + ((c ^ t) << 4);
                src = srcs[a] + (size_t)t * 2048 + c * 16;
            }
            cp_async16(smem_u32(&sb[st][a][0]) + dst, src);
        }
        cp_commit();
    };

    __syncthreads();            // sInj ready
    stage(0, 0);

    for (int jt = 0; jt < 8; jt++) {
        cp_wait<0>();
        __syncthreads();
        if (jt < 7) stage((jt + 1) & 1, jt + 1);

        const uint8_t* Xjh = sb[jt & 1][0];
        const uint8_t* Xjl = sb[jt & 1][1];
        const uint8_t* XTh = sb[jt & 1][2];
        const uint8_t* XTl = sb[jt & 1][3];

#pragma unroll 2
        for (int s2 = 0; s2 < 8; s2++) {
            const int js = s2 * 16;
            const int jabs = jt * 128 + js;

            // --- S = Xi · Xjᵀ (two n8 tiles) ---
            const int ro0 = (js + g) * 32 + tg * 4;
            const int ro1 = (js + 8 + g) * 32 + tg * 4;
            uint32_t bh0[2] = {*(const uint32_t*)(Xjh + ro0),
                               *(const uint32_t*)(Xjh + ro0 + 16)};
            uint32_t bl0[2] = {*(const uint32_t*)(Xjl + ro0),
                               *(const uint32_t*)(Xjl + ro0 + 16)};
            uint32_t bh1[2] = {*(const uint32_t*)(Xjh + ro1),
                               *(const uint32_t*)(Xjh + ro1 + 16)};
            uint32_t bl1[2] = {*(const uint32_t*)(Xjl + ro1),
                               *(const uint32_t*)(Xjl + ro1 + 16)};
            float s0[4] = {0.f, 0.f, 0.f, 0.f};
            float s1[4] = {0.f, 0.f, 0.f, 0.f};
            mma16816(s0, aih, bh0); mma16816(s0, aih, bl0); mma16816(s0, ail, bh0);
            mma16816(s1, aih, bh1); mma16816(s1, aih, bl1); mma16816(s1, ail, bh1);

            // --- sigmoid(beta * cos) ---
            const float* bp = beta + (size_t)r0 * 1024 + jabs + 2 * tg;
            float2 be00 = *(const float2*)(bp);
            float2 be01 = *(const float2*)(bp + 8);
            float2 be10 = *(const float2*)(bp + 8192);
            float2 be11 = *(const float2*)(bp + 8192 + 8);
            float2 nj0 = *(const float2*)&sInj[jabs + 2 * tg];
            float2 nj1 = *(const float2*)&sInj[jabs + 8 + 2 * tg];

#define SIG(z) (__fdividef(1.f, 1.f + __expf(-(z))))
            float p00 = SIG(be00.x * s0[0] * ni0 * nj0.x);
            float p01 = SIG(be00.y * s0[1] * ni0 * nj0.y);
            float p02 = SIG(be10.x * s0[2] * ni1 * nj0.x);
            float p03 = SIG(be10.y * s0[3] * ni1 * nj0.y);
            float p10 = SIG(be01.x * s1[0] * ni0 * nj1.x);
            float p11 = SIG(be01.y * s1[1] * ni0 * nj1.y);
            float p12 = SIG(be11.x * s1[2] * ni1 * nj1.x);
            float p13 = SIG(be11.y * s1[3] * ni1 * nj1.y);
#undef SIG

            // --- pack P into A-frags (hi + residual lo) ---
            uint32_t pah[4], pal[4];
            pah[0] = pack_bf16x2(p01, p00);
            pah[1] = pack_bf16x2(p03, p02);
            pah[2] = pack_bf16x2(p11, p10);
            pah[3] = pack_bf16x2(p13, p12);
            pal[0] = pack_bf16x2(p01 - bf16hi_f(pah[0]), p00 - bf16lo_f(pah[0]));
            pal[1] = pack_bf16x2(p03 - bf16hi_f(pah[1]), p02 - bf16lo_f(pah[1]));
            pal[2] = pack_bf16x2(p11 - bf16hi_f(pah[2]), p10 - bf16lo_f(pah[2]));
            pal[3] = pack_bf16x2(p13 - bf16hi_f(pah[3]), p12 - bf16lo_f(pah[3]));

            // --- O += P · X  (B-frags from swizzled XT) ---
            const int pi = (js >> 1) + tg;
            const int c0 = pi >> 2, w0 = pi & 3;
            const int c1 = (pi + 4) >> 2, w1 = (pi + 4) & 3;
            const int off00 = g * 256 + ((c0 ^ g) << 4) + w0 * 4;
            const int off01 = g * 256 + ((c1 ^ g) << 4) + w1 * 4;
            const int off10 = (8 + g) * 256 + ((c0 ^ (8 + g)) << 4) + w0 * 4;
            const int off11 = (8 + g) * 256 + ((c1 ^ (8 + g)) << 4) + w1 * 4;
            uint32_t th0[2] = {*(const uint32_t*)(XTh + off00),
                               *(const uint32_t*)(XTh + off01)};
            uint32_t tl0[2] = {*(const uint32_t*)(XTl + off00),
                               *(const uint32_t*)(XTl + off01)};
            uint32_t th1[2] = {*(const uint32_t*)(XTh + off10),
                               *(const uint32_t*)(XTh + off11)};
            uint32_t tl1[2] = {*(const uint32_t*)(XTl + off10),
                               *(const uint32_t*)(XTl + off11)};
            mma16816(o0, pah, th0); mma16816(o0, pah, tl0); mma16816(o0, pal, th0);
            mma16816(o1, pah, th1); mma16816(o1, pah, tl1); mma16816(o1, pal, th1);
        }
    }

    // epilogue: O (16i x 16t per warp) -> g_cos[b][i][t][ch]
    {
        float* base = g_cos + (((size_t)(b * 1024 + r0) * 16) * 16) + ch;
        // row stride = 256 floats; t stride = 16 floats
        base[(2 * tg) * 16]           = o0[0];
        base[(2 * tg + 1) * 16]       = o0[1];
        base[2048 + (2 * tg) * 16]     = o0[2];   // row r0+8: 8*256
        base[2048 + (2 * tg + 1) * 16] = o0[3];
        base[(8 + 2 * tg) * 16]           = o1[0];
        base[(8 + 2 * tg + 1) * 16]       = o1[1];
        base[2048 + (8 + 2 * tg) * 16]     = o1[2];
        base[2048 + (8 + 2 * tg + 1) * 16] = o1[3];
    }
}

// =============================================================================
// K4: fuse + channel softmax
// =============================================================================
__global__ __launch_bounds__(256) void k4_final(const float* __restrict__ x,
                                                float* __restrict__ out)
{
    const int idx = blockIdx.x * 256 + threadIdx.x;
    const int t = idx & 15;
    const int i = (idx >> 4) & 1023;
    const int b = idx >> 14;

    const float* gc = g_gc + (size_t)idx * 16;
    const float* cs = g_cos + (size_t)idx * 16;

    float g[16];
#pragma unroll
    for (int c = 0; c < 16; c++) {
        float xv = x[(((b << 4) + c) << 14) + (i << 4) + t];
        float r = gc[c] + xv;
        r = r > 0.f ? r : 0.f;
        g[c] = cs[c] * r;
    }
    float m = g[0];
#pragma unroll
    for (int c = 1; c < 16; c++) m = fmaxf(m, g[c]);
    float s = 0.f;
#pragma unroll
    for (int c = 0; c < 16; c++) {
        float e = __expf(g[c] - m);
        g[c] = e;
        s += e;
    }
    float rs = __fdividef(1.f, s);
#pragma unroll
    for (int c = 0; c < 16; c++)
        out[(((b << 4) + c) << 14) + (i << 4) + t] = g[c] * rs;
}

// =============================================================================
extern "C" void kernel_launch(void* const* d_in, const int* in_sizes, int n_in,
                              void* d_out, int out_size)
{
    const float* x     = (const float*)d_in[0];
    const float* beta  = (const float*)d_in[1];
    const float* theta = (const float*)d_in[2];
    const float* bias  = (const float*)d_in[3];
    const float* Lk    = (const float*)d_in[4];
    float* out = (float*)d_out;

    p1_convA<<<64, 256>>>(x);
    p2_convB<<<dim3(64, 32), 256>>>(Lk);
    k1_mma<<<dim3(16, 8), 256>>>();
    k3t<<<dim3(8, 64), 256>>>(beta);
    k2_fold<<<256, 256>>>(x, theta, bias);
    k4_final<<<256, 256>>>(x, out);
}

// round 5
// speedup vs baseline: 2.1126x; 1.1767x over previous
#include <cuda_runtime.h>
#include <cuda_bf16.h>
#include <cstdint>

// Problem constants: B=4, C=T=16, n=1024, KS=3
// out = softmax_ch( cos_att * relu(x_gc_t + x) )

// ---------------- scratch (device globals) ----------------------------------
__device__ float g_XM[1024 * 2048];                        // GEMM result
__device__ float g_gc[4 * 1024 * 16 * 16];                 // [b][i][t][ch]
__device__ float g_cos[4 * 1024 * 16 * 16];                // [b][i][t][ch]
__device__ __align__(16) __nv_bfloat16 g_Ahi[1024 * 1024]; // x_tmp hi, K-major
__device__ __align__(16) __nv_bfloat16 g_Alo[1024 * 1024];
__device__ __align__(16) __nv_bfloat16 g_Bhi[2048 * 1024]; // Lk2^T hi, K-major
__device__ __align__(16) __nv_bfloat16 g_Blo[2048 * 1024];
__device__ __align__(16) __nv_bfloat16 g_Xbfh[64 * 1024 * 16]; // x[bc][i][t] hi
__device__ __align__(16) __nv_bfloat16 g_Xbfl[64 * 1024 * 16]; // lo
__device__ __align__(16) __nv_bfloat16 g_XTh[64 * 16 * 1024];  // x[bc][t][i] hi
__device__ __align__(16) __nv_bfloat16 g_XTl[64 * 16 * 1024];  // lo
__device__ float g_inorm[64 * 1024];                           // 1/||x_i||

// ---------------- helpers ----------------------------------------------------
__device__ __forceinline__ uint32_t smem_u32(const void* p) {
    uint32_t a;
    asm("{ .reg .u64 t; cvta.to.shared.u64 t, %1; cvt.u32.u64 %0, t; }"
        : "=r"(a) : "l"(p));
    return a;
}
__device__ __forceinline__ void cp_async16(uint32_t dst, const void* src) {
    asm volatile("cp.async.cg.shared.global [%0], [%1], 16;" :: "r"(dst), "l"(src));
}
__device__ __forceinline__ void cp_commit() {
    asm volatile("cp.async.commit_group;" ::: "memory");
}
template <int N> __device__ __forceinline__ void cp_wait() {
    asm volatile("cp.async.wait_group %0;" :: "n"(N) : "memory");
}
__device__ __forceinline__ void mma16816(float* d, const uint32_t* a,
                                         const uint32_t* b) {
    asm volatile(
        "mma.sync.aligned.m16n8k16.row.col.f32.bf16.bf16.f32 "
        "{%0,%1,%2,%3}, {%4,%5,%6,%7}, {%8,%9}, {%0,%1,%2,%3};\n"
        : "+f"(d[0]), "+f"(d[1]), "+f"(d[2]), "+f"(d[3])
        : "r"(a[0]), "r"(a[1]), "r"(a[2]), "r"(a[3]), "r"(b[0]), "r"(b[1]));
}
__device__ __forceinline__ void ldsm_x4(uint32_t* r, uint32_t addr) {
    asm volatile("ldmatrix.sync.aligned.m8n8.x4.shared.b16 {%0,%1,%2,%3}, [%4];"
                 : "=r"(r[0]), "=r"(r[1]), "=r"(r[2]), "=r"(r[3]) : "r"(addr));
}
__device__ __forceinline__ uint32_t pack_bf16x2(float hi, float lo) {
    uint32_t r;
    asm("cvt.rn.satfinite.bf16x2.f32 %0, %1, %2;" : "=r"(r) : "f"(hi), "f"(lo));
    return r;
}
__device__ __forceinline__ float bf16lo_f(uint32_t u) {
    return __uint_as_float(u << 16);
}
__device__ __forceinline__ float bf16hi_f(uint32_t u) {
    return __uint_as_float(u & 0xFFFF0000u);
}
// sigmoid(z) = 0.5 * tanh(z/2) + 0.5  (1 MUFU)
__device__ __forceinline__ float sig_tanh(float z) {
    float t;
    asm("tanh.approx.f32 %0, %1;" : "=f"(t) : "f"(0.5f * z));
    return fmaf(0.5f, t, 0.5f);
}

// =============================================================================
// P1: x -> (a) g_Ahi/lo  A[r][k=i], r=(bc)*16+t
//          (b) g_Xbfh/l  [bc][i][t] + g_inorm
//          (c) g_XTh/l   [bc][t][i]
// =============================================================================
__global__ __launch_bounds__(256) void p1_convA(const float* __restrict__ x)
{
    __shared__ float s[16][258];
    const int g = blockIdx.x;          // 0..63 = bc
    const int tid = threadIdx.x;
    for (int c = 0; c < 4; c++) {
        __syncthreads();
#pragma unroll
        for (int it = 0; it < 16; it++) {
            int idx = tid + it * 256;                 // i_local*16 + t
            float v = x[g * 16384 + c * 4096 + idx];
            s[idx & 15][idx >> 4] = v;
        }
        __syncthreads();
        // (a) A matrices: row = g*16 + t, cols i
        {
            const int rl = tid >> 4;
            const int kk0 = (tid & 15) * 16;
            alignas(16) __nv_bfloat16 hb[16], lb[16];
#pragma unroll
            for (int q = 0; q < 16; q++) {
                float v = s[rl][kk0 + q];
                __nv_bfloat16 h = __float2bfloat16(v);
                hb[q] = h;
                lb[q] = __float2bfloat16(v - __bfloat162float(h));
            }
            size_t off = (size_t)(g * 16 + rl) * 1024 + c * 256 + kk0;
            *(uint4*)(g_Ahi + off)     = *(uint4*)(hb);
            *(uint4*)(g_Ahi + off + 8) = *(uint4*)(hb + 8);
            *(uint4*)(g_Alo + off)     = *(uint4*)(lb);
            *(uint4*)(g_Alo + off + 8) = *(uint4*)(lb + 8);
        }
        // (b) Xbf rows [i][t] + inv norm
        {
            const int i = c * 256 + tid;
            alignas(16) __nv_bfloat16 hb[16], lb[16];
            float s2 = 0.f;
#pragma unroll
            for (int t = 0; t < 16; t++) {
                float v = s[t][tid];
                s2 = fmaf(v, v, s2);
                __nv_bfloat16 h = __float2bfloat16(v);
                hb[t] = h;
                lb[t] = __float2bfloat16(v - __bfloat162float(h));
            }
            g_inorm[g * 1024 + i] = rsqrtf(s2);
            size_t off = (size_t)(g * 1024 + i) * 16;
            *(uint4*)(g_Xbfh + off)     = *(uint4*)(hb);
            *(uint4*)(g_Xbfh + off + 8) = *(uint4*)(hb + 8);
            *(uint4*)(g_Xbfl + off)     = *(uint4*)(lb);
            *(uint4*)(g_Xbfl + off + 8) = *(uint4*)(lb + 8);
        }
        // (c) XT rows [t][i]
        {
            const int t = tid >> 4;
            const int ib = (tid & 15) * 16;
            alignas(16) __nv_bfloat16 hb[16], lb[16];
#pragma unroll
            for (int q = 0; q < 16; q++) {
                float v = s[t][ib + q];
                __nv_bfloat16 h = __float2bfloat16(v);
                hb[q] = h;
                lb[q] = __float2bfloat16(v - __bfloat162float(h));
            }
            size_t off = (size_t)(g * 16 + t) * 1024 + c * 256 + ib;
            *(uint4*)(g_XTh + off)     = *(uint4*)(hb);
            *(uint4*)(g_XTh + off + 8) = *(uint4*)(hb + 8);
            *(uint4*)(g_XTl + off)     = *(uint4*)(lb);
            *(uint4*)(g_XTl + off + 8) = *(uint4*)(lb + 8);
        }
    }
}

// =============================================================================
// P2: Lk2 transpose -> B_hi/B_lo.  Bt[j][k] = Lk[k*3072 + 1024 + j]
// =============================================================================
__global__ __launch_bounds__(256) void p2_convB(const float* __restrict__ Lk)
{
    __shared__ float s[32][33];
    const int jt = blockIdx.x;
    const int kt = blockIdx.y;
    const int tx = threadIdx.x & 31, ty = threadIdx.x >> 5;
#pragma unroll
    for (int p = 0; p < 4; p++) {
        int ky = ty + p * 8;
        s[tx][ky] = Lk[(kt * 32 + ky) * 3072 + 1024 + jt * 32 + tx];
    }
    __syncthreads();
#pragma unroll
    for (int p = 0; p < 4; p++) {
        int jy = ty + p * 8;
        float v = s[jy][tx];
        __nv_bfloat16 h = __float2bfloat16(v);
        size_t off = (size_t)(jt * 32 + jy) * 1024 + kt * 32 + tx;
        g_Bhi[off] = h;
        g_Blo[off] = __float2bfloat16(v - __bfloat162float(h));
    }
}

// =============================================================================
// K1: split-bf16 HMMA GEMM. D[128x128]/CTA, grid(16,8), 256 thr.
// Fragments now via ldmatrix.x4 (conflict-free with the (c^((r>>2)&1)) swizzle),
// A hi/lo frags hoisted across the 3 passes: 12 LDSM/kt vs 72 LDS/kt before.
// =============================================================================
__global__ __launch_bounds__(256) void k1_mma()
{
    __shared__ __align__(16) uint8_t smem[2][4][4096];

    const int tid = threadIdx.x;
    const int wid = tid >> 5, lane = tid & 31;
    const int g = lane >> 2, tg = lane & 3;
    const int wm = (wid & 3) * 32;
    const int wn = (wid >> 2) * 64;
    const int row0 = blockIdx.y * 128;
    const int col0 = blockIdx.x * 128;

    const __nv_bfloat16* gsrc[4] = {
        g_Ahi + (size_t)row0 * 1024, g_Alo + (size_t)row0 * 1024,
        g_Bhi + (size_t)col0 * 1024, g_Blo + (size_t)col0 * 1024};

    float acc[2][8][4];
#pragma unroll
    for (int mt = 0; mt < 2; mt++)
#pragma unroll
        for (int nt = 0; nt < 8; nt++)
#pragma unroll
            for (int q = 0; q < 4; q++) acc[mt][nt][q] = 0.f;

    auto load_stage = [&](int s, int kt) {
#pragma unroll
        for (int q = 0; q < 4; q++) {
            int idx = tid + q * 256;
            int arr = idx >> 8;
            int rc  = idx & 255;
            int r   = rc >> 1;
            int c   = rc & 1;
            const void* src = gsrc[arr] + (size_t)r * 1024 + kt * 16 + c * 8;
            uint32_t dst = smem_u32(&smem[s][arr][0]) + r * 32 +
                           ((c * 16) ^ (((r >> 2) & 1) << 4));
            cp_async16(dst, src);
        }
        cp_commit();
    };

    // ldmatrix per-lane offsets (within a 4096B array)
    uint32_t offA[2], offB[4];
    {
        int arow = ((lane >> 3) & 1) * 8 + (lane & 7);
        int cA = lane >> 4;
        int brow = ((lane >> 4) << 3) + (lane & 7);
        int cB = (lane >> 3) & 1;
#pragma unroll
        for (int mt = 0; mt < 2; mt++) {
            int r = wm + mt * 16 + arow;
            offA[mt] = r * 32 + ((cA ^ ((r >> 2) & 1)) << 4);
        }
#pragma unroll
        for (int p = 0; p < 4; p++) {
            int r = wn + p * 16 + brow;
            offB[p] = r * 32 + ((cB ^ ((r >> 2) & 1)) << 4);
        }
    }

    load_stage(0, 0);

    for (int kt = 0; kt < 64; kt++) {
        if (kt + 1 < 64) load_stage((kt + 1) & 1, kt + 1);
        if (kt + 1 < 64) cp_wait<1>(); else cp_wait<0>();
        __syncthreads();

        const uint32_t base = smem_u32(&smem[kt & 1][0][0]);

        uint32_t ah[2][4], al[2][4], bh[4][4], bl[4][4];
#pragma unroll
        for (int mt = 0; mt < 2; mt++) {
            ldsm_x4(ah[mt], base + offA[mt]);
            ldsm_x4(al[mt], base + 4096 + offA[mt]);
        }
#pragma unroll
        for (int p = 0; p < 4; p++) {
            ldsm_x4(bh[p], base + 2 * 4096 + offB[p]);
            ldsm_x4(bl[p], base + 3 * 4096 + offB[p]);
        }

#pragma unroll
        for (int mt = 0; mt < 2; mt++)
#pragma unroll
            for (int nt = 0; nt < 8; nt++) {
                const uint32_t* bhw = &bh[nt >> 1][(nt & 1) * 2];
                const uint32_t* blw = &bl[nt >> 1][(nt & 1) * 2];
                mma16816(acc[mt][nt], ah[mt], bhw);
                mma16816(acc[mt][nt], ah[mt], blw);
                mma16816(acc[mt][nt], al[mt], bhw);
            }
        __syncthreads();
    }
#pragma unroll
    for (int mt = 0; mt < 2; mt++) {
#pragma unroll
        for (int nt = 0; nt < 8; nt++) {
            int r = row0 + wm + mt * 16 + g;
            int c = col0 + wn + nt * 8 + tg * 2;
            *(float2*)&g_XM[(size_t)r * 2048 + c] =
                make_float2(acc[mt][nt][0], acc[mt][nt][1]);
            *(float2*)&g_XM[(size_t)(r + 8) * 2048 + c] =
                make_float2(acc[mt][nt][2], acc[mt][nt][3]);
        }
    }
}

// =============================================================================
// K2: fold theta
// =============================================================================
__global__ __launch_bounds__(256) void k2_fold(const float* __restrict__ x,
                                               const float* __restrict__ theta,
                                               const float* __restrict__ bias)
{
    __shared__ float th[768];
    __shared__ float bs[16];
    const int tid = threadIdx.x;
    for (int q = tid; q < 768; q += 256) th[q] = theta[q];
    if (tid < 16) bs[tid] = bias[tid];
    __syncthreads();

    const int idx = blockIdx.x * 256 + tid;
    const int i   = idx & 1023;
    const int tau = (idx >> 10) & 15;
    const int b   = idx >> 14;

    const float* xr = x + (((b << 4) + tau) << 14) + (i << 4);
    float xrow[16];
#pragma unroll
    for (int q = 0; q < 4; q++)
        *(float4*)(xrow + 4 * q) = *(const float4*)(xr + 4 * q);

    float acc[16];
#pragma unroll
    for (int c = 0; c < 16; c++) acc[c] = bs[c];

    const int rbase = (b << 8) + (tau << 4);
#pragma unroll 4
    for (int tp = 0; tp < 16; ++tp) {
        const float* xm = g_XM + (size_t)(rbase + tp) * 2048 + i;
        float a0 = xrow[tp];
        float a1 = xm[0];
        float a2 = xm[1024];
        const float* t0 = th + tp * 48;
#pragma unroll
        for (int c = 0; c < 16; c++)
            acc[c] += a0 * t0[c] + a1 * t0[16 + c] + a2 * t0[32 + c];
    }

    float* dst = g_gc + ((size_t)b << 18) + (i << 8) + (tau << 4);
#pragma unroll
    for (int q = 0; q < 4; q++)
        *(float4*)(dst + 4 * q) = *(float4*)(acc + 4 * q);
}

// =============================================================================
// K3T: tensorized attention, ldmatrix B-frags + tanh sigmoid.
// grid (8 i-tiles, 64 bc), 256 thr. Xj stored with (c^((j>>2)&1)) swizzle,
// XT with (c^t) swizzle — both give conflict-free LDSM phases.
// =============================================================================
__global__ __launch_bounds__(256) void k3t(const float* __restrict__ beta)
{
    __shared__ __align__(16) uint8_t sb[2][4][4096]; // [stage][Xjh,Xjl,XTh,XTl]
    __shared__ float sInj[1024];

    const int tid  = threadIdx.x;
    const int lane = tid & 31, wid = tid >> 5;
    const int g = lane >> 2, tg = lane & 3;
    const int bc = blockIdx.y;
    const int i0 = blockIdx.x * 128;
    const int b  = bc >> 4, ch = bc & 15;

    for (int q = tid; q < 1024; q += 256) sInj[q] = g_inorm[bc * 1024 + q];

    // Xi A-fragments (k = t = 16) + inverse row norms
    const int r0 = i0 + wid * 16 + g;
    uint32_t aih[4], ail[4];
    {
        const uint32_t* Xh = (const uint32_t*)(g_Xbfh + ((size_t)bc * 1024 + r0) * 16);
        const uint32_t* Xl = (const uint32_t*)(g_Xbfl + ((size_t)bc * 1024 + r0) * 16);
        aih[0] = Xh[tg];      aih[1] = Xh[64 + tg];
        aih[2] = Xh[tg + 4];  aih[3] = Xh[64 + tg + 4];
        ail[0] = Xl[tg];      ail[1] = Xl[64 + tg];
        ail[2] = Xl[tg + 4];  ail[3] = Xl[64 + tg + 4];
    }
    const float ni0 = g_inorm[bc * 1024 + r0];
    const float ni1 = g_inorm[bc * 1024 + r0 + 8];

    float o0[4] = {0.f, 0.f, 0.f, 0.f};
    float o1[4] = {0.f, 0.f, 0.f, 0.f};

    // ldmatrix per-lane constants
    const int jr = ((lane >> 4) << 3) + (lane & 7);    // 0..15
    const int cS = (lane >> 3) & 1;
    const uint32_t offS = (uint32_t)(jr * 32 + ((cS ^ ((jr >> 2) & 1)) << 4));
    const int tl = jr;                                  // PV: t lane (0..15)
    const int cbit = (lane >> 3) & 1;

    auto stage = [&](int st, int jt) {
        const size_t xb = ((size_t)bc * 1024 + jt * 128) * 32;   // bytes
        const size_t tb = ((size_t)bc * 16384 + jt * 128) * 2;   // bytes
        const char* srcs[4] = {(const char*)g_Xbfh + xb, (const char*)g_Xbfl + xb,
                               (const char*)g_XTh + tb,  (const char*)g_XTl + tb};
#pragma unroll
        for (int a = 0; a < 4; a++) {
            int q = tid;                  // 0..255 chunks per array
            uint32_t dst;
            const char* src;
            if (a < 2) {
                int j = q >> 1, c = q & 1;
                dst = (uint32_t)(j * 32 + ((c ^ ((j >> 2) & 1)) << 4));
                src = srcs[a] + (size_t)j * 32 + c * 16;
            } else {
                int t = q >> 4, c = q & 15;
                dst = (uint32_t)(t * 256 + ((c ^ t) << 4));
                src = srcs[a] + (size_t)t * 2048 + c * 16;
            }
            cp_async16(smem_u32(&sb[st][a][0]) + dst, src);
        }
        cp_commit();
    };

    __syncthreads();            // sInj ready
    stage(0, 0);

    for (int jt = 0; jt < 8; jt++) {
        cp_wait<0>();
        __syncthreads();
        if (jt < 7) stage((jt + 1) & 1, jt + 1);

        const uint32_t sbase = smem_u32(&sb[jt & 1][0][0]);

#pragma unroll 2
        for (int s2 = 0; s2 < 8; s2++) {
            const int js = s2 * 16;
            const int jabs = jt * 128 + js;

            // --- S = Xi · Xjᵀ (two n8 tiles) via 2 LDSM.x4 ---
            uint32_t bh4[4], bl4[4];
            ldsm_x4(bh4, sbase + js * 32 + offS);
            ldsm_x4(bl4, sbase + 4096 + js * 32 + offS);
            float s0[4] = {0.f, 0.f, 0.f, 0.f};
            float s1[4] = {0.f, 0.f, 0.f, 0.f};
            mma16816(s0, aih, &bh4[0]); mma16816(s0, aih, &bl4[0]);
            mma16816(s0, ail, &bh4[0]);
            mma16816(s1, aih, &bh4[2]); mma16816(s1, aih, &bl4[2]);
            mma16816(s1, ail, &bh4[2]);

            // --- sigmoid(beta * cos) : 1 MUFU each via tanh ---
            const float* bp = beta + (size_t)r0 * 1024 + jabs + 2 * tg;
            float2 be00 = *(const float2*)(bp);
            float2 be01 = *(const float2*)(bp + 8);
            float2 be10 = *(const float2*)(bp + 8192);
            float2 be11 = *(const float2*)(bp + 8192 + 8);
            float2 nj0 = *(const float2*)&sInj[jabs + 2 * tg];
            float2 nj1 = *(const float2*)&sInj[jabs + 8 + 2 * tg];

            float p00 = sig_tanh(be00.x * s0[0] * ni0 * nj0.x);
            float p01 = sig_tanh(be00.y * s0[1] * ni0 * nj0.y);
            float p02 = sig_tanh(be10.x * s0[2] * ni1 * nj0.x);
            float p03 = sig_tanh(be10.y * s0[3] * ni1 * nj0.y);
            float p10 = sig_tanh(be01.x * s1[0] * ni0 * nj1.x);
            float p11 = sig_tanh(be01.y * s1[1] * ni0 * nj1.y);
            float p12 = sig_tanh(be11.x * s1[2] * ni1 * nj1.x);
            float p13 = sig_tanh(be11.y * s1[3] * ni1 * nj1.y);

            // --- pack P into A-frags (hi + residual lo) ---
            uint32_t pah[4], pal[4];
            pah[0] = pack_bf16x2(p01, p00);
            pah[1] = pack_bf16x2(p03, p02);
            pah[2] = pack_bf16x2(p11, p10);
            pah[3] = pack_bf16x2(p13, p12);
            pal[0] = pack_bf16x2(p01 - bf16hi_f(pah[0]), p00 - bf16lo_f(pah[0]));
            pal[1] = pack_bf16x2(p03 - bf16hi_f(pah[1]), p02 - bf16lo_f(pah[1]));
            pal[2] = pack_bf16x2(p11 - bf16hi_f(pah[2]), p10 - bf16lo_f(pah[2]));
            pal[3] = pack_bf16x2(p13 - bf16hi_f(pah[3]), p12 - bf16lo_f(pah[3]));

            // --- O += P · X : B-frags via 2 LDSM.x4 from swizzled XT ---
            const uint32_t cj = 2 * s2 + cbit;
            const uint32_t offP = (uint32_t)(tl * 256 + ((cj ^ tl) << 4));
            uint32_t th4[4], tl4[4];
            ldsm_x4(th4, sbase + 2 * 4096 + offP);
            ldsm_x4(tl4, sbase + 3 * 4096 + offP);
            mma16816(o0, pah, &th4[0]); mma16816(o0, pah, &tl4[0]);
            mma16816(o0, pal, &th4[0]);
            mma16816(o1, pah, &th4[2]); mma16816(o1, pah, &tl4[2]);
            mma16816(o1, pal, &th4[2]);
        }
    }

    // epilogue: O (16i x 16t per warp) -> g_cos[b][i][t][ch]
    {
        float* base = g_cos + (((size_t)(b * 1024 + r0) * 16) * 16) + ch;
        base[(2 * tg) * 16]            = o0[0];
        base[(2 * tg + 1) * 16]        = o0[1];
        base[2048 + (2 * tg) * 16]     = o0[2];
        base[2048 + (2 * tg + 1) * 16] = o0[3];
        base[(8 + 2 * tg) * 16]            = o1[0];
        base[(8 + 2 * tg + 1) * 16]        = o1[1];
        base[2048 + (8 + 2 * tg) * 16]     = o1[2];
        base[2048 + (8 + 2 * tg + 1) * 16] = o1[3];
    }
}

// =============================================================================
// K4: fuse + channel softmax
// =============================================================================
__global__ __launch_bounds__(256) void k4_final(const float* __restrict__ x,
                                                float* __restrict__ out)
{
    const int idx = blockIdx.x * 256 + threadIdx.x;
    const int t = idx & 15;
    const int i = (idx >> 4) & 1023;
    const int b = idx >> 14;

    const float* gc = g_gc + (size_t)idx * 16;
    const float* cs = g_cos + (size_t)idx * 16;

    float g[16];
#pragma unroll
    for (int c = 0; c < 16; c++) {
        float xv = x[(((b << 4) + c) << 14) + (i << 4) + t];
        float r = gc[c] + xv;
        r = r > 0.f ? r : 0.f;
        g[c] = cs[c] * r;
    }
    float m = g[0];
#pragma unroll
    for (int c = 1; c < 16; c++) m = fmaxf(m, g[c]);
    float s = 0.f;
#pragma unroll
    for (int c = 0; c < 16; c++) {
        float e = __expf(g[c] - m);
        g[c] = e;
        s += e;
    }
    float rs = __fdividef(1.f, s);
#pragma unroll
    for (int c = 0; c < 16; c++)
        out[(((b << 4) + c) << 14) + (i << 4) + t] = g[c] * rs;
}

// =============================================================================
extern "C" void kernel_launch(void* const* d_in, const int* in_sizes, int n_in,
                              void* d_out, int out_size)
{
    const float* x     = (const float*)d_in[0];
    const float* beta  = (const float*)d_in[1];
    const float* theta = (const float*)d_in[2];
    const float* bias  = (const float*)d_in[3];
    const float* Lk    = (const float*)d_in[4];
    float* out = (float*)d_out;

    p1_convA<<<64, 256>>>(x);
    p2_convB<<<dim3(64, 32), 256>>>(Lk);
    k1_mma<<<dim3(16, 8), 256>>>();
    k3t<<<dim3(8, 64), 256>>>(beta);
    k2_fold<<<256, 256>>>(x, theta, bias);
    k4_final<<<256, 256>>>(x, out);
}

// round 6
// speedup vs baseline: 2.1235x; 1.0051x over previous
#include <cuda_runtime.h>
#include <cuda_bf16.h>
#include <cstdint>

// Problem constants: B=4, C=T=16, n=1024, KS=3
// out = softmax_ch( cos_att * relu(x_gc_t + x) )

// ---------------- scratch (device globals) ----------------------------------
__device__ float g_XM[1024 * 2048];                        // GEMM result
__device__ float g_gc[4 * 1024 * 16 * 16];                 // [b][i][t][ch]
__device__ float g_cos[4 * 1024 * 16 * 16];                // [b][i][t][ch]
__device__ __align__(16) __nv_bfloat16 g_Ahi[1024 * 1024]; // x_tmp hi, K-major
__device__ __align__(16) __nv_bfloat16 g_Alo[1024 * 1024];
__device__ __align__(16) __nv_bfloat16 g_Bhi[2048 * 1024]; // Lk2^T hi, K-major
__device__ __align__(16) __nv_bfloat16 g_Blo[2048 * 1024];
__device__ __align__(16) __nv_bfloat16 g_Xbfh[64 * 1024 * 16]; // x[bc][i][t] hi
__device__ __align__(16) __nv_bfloat16 g_Xbfl[64 * 1024 * 16]; // lo
__device__ __align__(16) __nv_bfloat16 g_XTh[64 * 16 * 1024];  // x[bc][t][i] hi
__device__ __align__(16) __nv_bfloat16 g_XTl[64 * 16 * 1024];  // lo
__device__ float g_inorm[64 * 1024];                           // 1/||x_i||
__device__ __align__(16) float4 g_bperm[262144];               // beta, frag order

// ---------------- helpers ----------------------------------------------------
__device__ __forceinline__ uint32_t smem_u32(const void* p) {
    uint32_t a;
    asm("{ .reg .u64 t; cvta.to.shared.u64 t, %1; cvt.u32.u64 %0, t; }"
        : "=r"(a) : "l"(p));
    return a;
}
__device__ __forceinline__ void cp_async16(uint32_t dst, const void* src) {
    asm volatile("cp.async.cg.shared.global [%0], [%1], 16;" :: "r"(dst), "l"(src));
}
__device__ __forceinline__ void cp_commit() {
    asm volatile("cp.async.commit_group;" ::: "memory");
}
template <int N> __device__ __forceinline__ void cp_wait() {
    asm volatile("cp.async.wait_group %0;" :: "n"(N) : "memory");
}
__device__ __forceinline__ void mma16816(float* d, const uint32_t* a,
                                         const uint32_t* b) {
    asm volatile(
        "mma.sync.aligned.m16n8k16.row.col.f32.bf16.bf16.f32 "
        "{%0,%1,%2,%3}, {%4,%5,%6,%7}, {%8,%9}, {%0,%1,%2,%3};\n"
        : "+f"(d[0]), "+f"(d[1]), "+f"(d[2]), "+f"(d[3])
        : "r"(a[0]), "r"(a[1]), "r"(a[2]), "r"(a[3]), "r"(b[0]), "r"(b[1]));
}
__device__ __forceinline__ void ldsm_x4(uint32_t* r, uint32_t addr) {
    asm volatile("ldmatrix.sync.aligned.m8n8.x4.shared.b16 {%0,%1,%2,%3}, [%4];"
                 : "=r"(r[0]), "=r"(r[1]), "=r"(r[2]), "=r"(r[3]) : "r"(addr));
}
__device__ __forceinline__ uint32_t pack_bf16x2(float hi, float lo) {
    uint32_t r;
    asm("cvt.rn.satfinite.bf16x2.f32 %0, %1, %2;" : "=r"(r) : "f"(hi), "f"(lo));
    return r;
}
__device__ __forceinline__ float bf16lo_f(uint32_t u) {
    return __uint_as_float(u << 16);
}
__device__ __forceinline__ float bf16hi_f(uint32_t u) {
    return __uint_as_float(u & 0xFFFF0000u);
}
// sigmoid(z) = 0.5 * tanh(z/2) + 0.5  (1 MUFU)
__device__ __forceinline__ float sig_tanh(float z) {
    float t;
    asm("tanh.approx.f32 %0, %1;" : "=f"(t) : "f"(0.5f * z));
    return fmaf(0.5f, t, 0.5f);
}

// =============================================================================
// P1: x -> (a) g_Ahi/lo, (b) g_Xbfh/l + g_inorm, (c) g_XTh/l
// =============================================================================
__global__ __launch_bounds__(256) void p1_convA(const float* __restrict__ x)
{
    __shared__ float s[16][258];
    const int g = blockIdx.x;          // 0..63 = bc
    const int tid = threadIdx.x;
    for (int c = 0; c < 4; c++) {
        __syncthreads();
#pragma unroll
        for (int it = 0; it < 16; it++) {
            int idx = tid + it * 256;                 // i_local*16 + t
            float v = x[g * 16384 + c * 4096 + idx];
            s[idx & 15][idx >> 4] = v;
        }
        __syncthreads();
        {   // (a)
            const int rl = tid >> 4;
            const int kk0 = (tid & 15) * 16;
            alignas(16) __nv_bfloat16 hb[16], lb[16];
#pragma unroll
            for (int q = 0; q < 16; q++) {
                float v = s[rl][kk0 + q];
                __nv_bfloat16 h = __float2bfloat16(v);
                hb[q] = h;
                lb[q] = __float2bfloat16(v - __bfloat162float(h));
            }
            size_t off = (size_t)(g * 16 + rl) * 1024 + c * 256 + kk0;
            *(uint4*)(g_Ahi + off)     = *(uint4*)(hb);
            *(uint4*)(g_Ahi + off + 8) = *(uint4*)(hb + 8);
            *(uint4*)(g_Alo + off)     = *(uint4*)(lb);
            *(uint4*)(g_Alo + off + 8) = *(uint4*)(lb + 8);
        }
        {   // (b)
            const int i = c * 256 + tid;
            alignas(16) __nv_bfloat16 hb[16], lb[16];
            float s2 = 0.f;
#pragma unroll
            for (int t = 0; t < 16; t++) {
                float v = s[t][tid];
                s2 = fmaf(v, v, s2);
                __nv_bfloat16 h = __float2bfloat16(v);
                hb[t] = h;
                lb[t] = __float2bfloat16(v - __bfloat162float(h));
            }
            g_inorm[g * 1024 + i] = rsqrtf(s2);
            size_t off = (size_t)(g * 1024 + i) * 16;
            *(uint4*)(g_Xbfh + off)     = *(uint4*)(hb);
            *(uint4*)(g_Xbfh + off + 8) = *(uint4*)(hb + 8);
            *(uint4*)(g_Xbfl + off)     = *(uint4*)(lb);
            *(uint4*)(g_Xbfl + off + 8) = *(uint4*)(lb + 8);
        }
        {   // (c)
            const int t = tid >> 4;
            const int ib = (tid & 15) * 16;
            alignas(16) __nv_bfloat16 hb[16], lb[16];
#pragma unroll
            for (int q = 0; q < 16; q++) {
                float v = s[t][ib + q];
                __nv_bfloat16 h = __float2bfloat16(v);
                hb[q] = h;
                lb[q] = __float2bfloat16(v - __bfloat162float(h));
            }
            size_t off = (size_t)(g * 16 + t) * 1024 + c * 256 + ib;
            *(uint4*)(g_XTh + off)     = *(uint4*)(hb);
            *(uint4*)(g_XTh + off + 8) = *(uint4*)(hb + 8);
            *(uint4*)(g_XTl + off)     = *(uint4*)(lb);
            *(uint4*)(g_XTl + off + 8) = *(uint4*)(lb + 8);
        }
    }
}

// =============================================================================
// P2: Lk2 transpose -> B_hi/B_lo.
// =============================================================================
__global__ __launch_bounds__(256) void p2_convB(const float* __restrict__ Lk)
{
    __shared__ float s[32][33];
    const int jt = blockIdx.x;
    const int kt = blockIdx.y;
    const int tx = threadIdx.x & 31, ty = threadIdx.x >> 5;
#pragma unroll
    for (int p = 0; p < 4; p++) {
        int ky = ty + p * 8;
        s[tx][ky] = Lk[(kt * 32 + ky) * 3072 + 1024 + jt * 32 + tx];
    }
    __syncthreads();
#pragma unroll
    for (int p = 0; p < 4; p++) {
        int jy = ty + p * 8;
        float v = s[jy][tx];
        __nv_bfloat16 h = __float2bfloat16(v);
        size_t off = (size_t)(jt * 32 + jy) * 1024 + kt * 32 + tx;
        g_Bhi[off] = h;
        g_Blo[off] = __float2bfloat16(v - __bfloat162float(h));
    }
}

// =============================================================================
// P3: beta -> fragment-ordered g_bperm.
// idx -> (ib, js, lane): lane=idx&31, js=(idx>>5)&63, ib=idx>>11.
// float4 #0 = rows ib*16+g     cols {2tg,2tg+1,8+2tg,8+2tg+1} of j-block js
// float4 #1 = rows ib*16+8+g   same cols
// =============================================================================
__global__ __launch_bounds__(256) void p3_permBeta(const float* __restrict__ beta)
{
    const int idx = blockIdx.x * 256 + threadIdx.x;    // 0..131071
    const int lane = idx & 31;
    const int js = (idx >> 5) & 63;
    const int ib = idx >> 11;
    const int g = lane >> 2, tg = lane & 3;
    const int r0 = ib * 16 + g, r1 = r0 + 8;
    const int c0 = js * 16 + 2 * tg, c1 = c0 + 8;
    const float* b0 = beta + (size_t)r0 * 1024;
    const float* b1 = beta + (size_t)r1 * 1024;
    float2 a0 = *(const float2*)(b0 + c0);
    float2 a1 = *(const float2*)(b0 + c1);
    float2 a2 = *(const float2*)(b1 + c0);
    float2 a3 = *(const float2*)(b1 + c1);
    g_bperm[idx * 2]     = make_float4(a0.x, a0.y, a1.x, a1.y);
    g_bperm[idx * 2 + 1] = make_float4(a2.x, a2.y, a3.x, a3.y);
}

// =============================================================================
// K1: split-bf16 HMMA GEMM, 3-stage cp.async pipeline, 1 sync/kt.
// D[128x128]/CTA, grid(16,8), 256 thr, 48KB static smem.
// =============================================================================
__global__ __launch_bounds__(256) void k1_mma()
{
    __shared__ __align__(16) uint8_t smem[3][4][4096];

    const int tid = threadIdx.x;
    const int wid = tid >> 5, lane = tid & 31;
    const int g = lane >> 2, tg = lane & 3;
    const int wm = (wid & 3) * 32;
    const int wn = (wid >> 2) * 64;
    const int row0 = blockIdx.y * 128;
    const int col0 = blockIdx.x * 128;

    const __nv_bfloat16* gsrc[4] = {
        g_Ahi + (size_t)row0 * 1024, g_Alo + (size_t)row0 * 1024,
        g_Bhi + (size_t)col0 * 1024, g_Blo + (size_t)col0 * 1024};

    float acc[2][8][4];
#pragma unroll
    for (int mt = 0; mt < 2; mt++)
#pragma unroll
        for (int nt = 0; nt < 8; nt++)
#pragma unroll
            for (int q = 0; q < 4; q++) acc[mt][nt][q] = 0.f;

    auto load_stage = [&](int s, int kt) {
#pragma unroll
        for (int q = 0; q < 4; q++) {
            int idx = tid + q * 256;
            int arr = idx >> 8;
            int rc  = idx & 255;
            int r   = rc >> 1;
            int c   = rc & 1;
            const void* src = gsrc[arr] + (size_t)r * 1024 + kt * 16 + c * 8;
            uint32_t dst = smem_u32(&smem[s][arr][0]) + r * 32 +
                           ((c * 16) ^ (((r >> 2) & 1) << 4));
            cp_async16(dst, src);
        }
        cp_commit();
    };

    // ldmatrix per-lane offsets (within a 4096B array)
    uint32_t offA[2], offB[4];
    {
        int arow = ((lane >> 3) & 1) * 8 + (lane & 7);
        int cA = lane >> 4;
        int brow = ((lane >> 4) << 3) + (lane & 7);
        int cB = (lane >> 3) & 1;
#pragma unroll
        for (int mt = 0; mt < 2; mt++) {
            int r = wm + mt * 16 + arow;
            offA[mt] = r * 32 + ((cA ^ ((r >> 2) & 1)) << 4);
        }
#pragma unroll
        for (int p = 0; p < 4; p++) {
            int r = wn + p * 16 + brow;
            offB[p] = r * 32 + ((cB ^ ((r >> 2) & 1)) << 4);
        }
    }

    load_stage(0, 0);
    load_stage(1, 1);

    int sread = 0;
    for (int kt = 0; kt < 64; kt++) {
        if (kt < 63) cp_wait<1>(); else cp_wait<0>();
        __syncthreads();
        if (kt + 2 < 64) {
            int sw = sread + 2; if (sw >= 3) sw -= 3;
            load_stage(sw, kt + 2);
        }

        const uint32_t base = smem_u32(&smem[sread][0][0]);

        uint32_t ah[2][4], al[2][4], bh[4][4], bl[4][4];
#pragma unroll
        for (int mt = 0; mt < 2; mt++) {
            ldsm_x4(ah[mt], base + offA[mt]);
            ldsm_x4(al[mt], base + 4096 + offA[mt]);
        }
#pragma unroll
        for (int p = 0; p < 4; p++) {
            ldsm_x4(bh[p], base + 2 * 4096 + offB[p]);
            ldsm_x4(bl[p], base + 3 * 4096 + offB[p]);
        }

#pragma unroll
        for (int mt = 0; mt < 2; mt++)
#pragma unroll
            for (int nt = 0; nt < 8; nt++) {
                const uint32_t* bhw = &bh[nt >> 1][(nt & 1) * 2];
                const uint32_t* blw = &bl[nt >> 1][(nt & 1) * 2];
                mma16816(acc[mt][nt], ah[mt], bhw);
                mma16816(acc[mt][nt], ah[mt], blw);
                mma16816(acc[mt][nt], al[mt], bhw);
            }
        sread = (sread + 1 == 3) ? 0 : sread + 1;
    }
#pragma unroll
    for (int mt = 0; mt < 2; mt++) {
#pragma unroll
        for (int nt = 0; nt < 8; nt++) {
            int r = row0 + wm + mt * 16 + g;
            int c = col0 + wn + nt * 8 + tg * 2;
            *(float2*)&g_XM[(size_t)r * 2048 + c] =
                make_float2(acc[mt][nt][0], acc[mt][nt][1]);
            *(float2*)&g_XM[(size_t)(r + 8) * 2048 + c] =
                make_float2(acc[mt][nt][2], acc[mt][nt][3]);
        }
    }
}

// =============================================================================
// K2: fold theta
// =============================================================================
__global__ __launch_bounds__(256) void k2_fold(const float* __restrict__ x,
                                               const float* __restrict__ theta,
                                               const float* __restrict__ bias)
{
    __shared__ float th[768];
    __shared__ float bs[16];
    const int tid = threadIdx.x;
    for (int q = tid; q < 768; q += 256) th[q] = theta[q];
    if (tid < 16) bs[tid] = bias[tid];
    __syncthreads();

    const int idx = blockIdx.x * 256 + tid;
    const int i   = idx & 1023;
    const int tau = (idx >> 10) & 15;
    const int b   = idx >> 14;

    const float* xr = x + (((b << 4) + tau) << 14) + (i << 4);
    float xrow[16];
#pragma unroll
    for (int q = 0; q < 4; q++)
        *(float4*)(xrow + 4 * q) = *(const float4*)(xr + 4 * q);

    float acc[16];
#pragma unroll
    for (int c = 0; c < 16; c++) acc[c] = bs[c];

    const int rbase = (b << 8) + (tau << 4);
#pragma unroll 4
    for (int tp = 0; tp < 16; ++tp) {
        const float* xm = g_XM + (size_t)(rbase + tp) * 2048 + i;
        float a0 = xrow[tp];
        float a1 = xm[0];
        float a2 = xm[1024];
        const float* t0 = th + tp * 48;
#pragma unroll
        for (int c = 0; c < 16; c++)
            acc[c] += a0 * t0[c] + a1 * t0[16 + c] + a2 * t0[32 + c];
    }

    float* dst = g_gc + ((size_t)b << 18) + (i << 8) + (tau << 4);
#pragma unroll
    for (int q = 0; q < 4; q++)
        *(float4*)(dst + 4 * q) = *(float4*)(acc + 4 * q);
}

// =============================================================================
// K3T: tensorized attention. Warp handles 32 i-rows (2 A-frag pairs),
// grid (4 i-tiles of 256, 64 bc). Beta via fragment-ordered g_bperm
// (2 coalesced LDG.128 per pair per step). ldmatrix B-frags shared
// across both pairs.
// =============================================================================
__global__ __launch_bounds__(256) void k3t()
{
    __shared__ __align__(16) uint8_t sb[2][4][4096]; // [stage][Xjh,Xjl,XTh,XTl]
    __shared__ float sInj[1024];

    const int tid  = threadIdx.x;
    const int lane = tid & 31, wid = tid >> 5;
    const int g = lane >> 2, tg = lane & 3;
    const int bc = blockIdx.y;
    const int i0 = blockIdx.x * 256;
    const int b  = bc >> 4, ch = bc & 15;

    for (int q = tid; q < 1024; q += 256) sInj[q] = g_inorm[bc * 1024 + q];

    const int rw = i0 + wid * 32;            // warp's first i-row
    const int ib0 = rw >> 4;                 // 16-row block index (pair 0)

    uint32_t aih[2][4], ail[2][4];
    float nia[2], nib[2];
#pragma unroll
    for (int p = 0; p < 2; p++) {
        const int r = rw + 16 * p + g;
        const uint32_t* Xh = (const uint32_t*)(g_Xbfh + ((size_t)bc * 1024 + r) * 16);
        const uint32_t* Xl = (const uint32_t*)(g_Xbfl + ((size_t)bc * 1024 + r) * 16);
        aih[p][0] = Xh[tg];      aih[p][1] = Xh[64 + tg];
        aih[p][2] = Xh[tg + 4];  aih[p][3] = Xh[64 + tg + 4];
        ail[p][0] = Xl[tg];      ail[p][1] = Xl[64 + tg];
        ail[p][2] = Xl[tg + 4];  ail[p][3] = Xl[64 + tg + 4];
        nia[p] = g_inorm[bc * 1024 + r];
        nib[p] = g_inorm[bc * 1024 + r + 8];
    }

    float o[2][2][4];
#pragma unroll
    for (int p = 0; p < 2; p++)
#pragma unroll
        for (int u = 0; u < 2; u++)
#pragma unroll
            for (int q = 0; q < 4; q++) o[p][u][q] = 0.f;

    // ldmatrix per-lane constants
    const int jr = ((lane >> 4) << 3) + (lane & 7);
    const int cS = (lane >> 3) & 1;
    const uint32_t offS = (uint32_t)(jr * 32 + ((cS ^ ((jr >> 2) & 1)) << 4));
    const int tl = jr;
    const int cbit = (lane >> 3) & 1;

    auto stage = [&](int st, int jt) {
        const size_t xb = ((size_t)bc * 1024 + jt * 128) * 32;   // bytes
        const size_t tb = ((size_t)bc * 16384 + jt * 128) * 2;   // bytes
        const char* srcs[4] = {(const char*)g_Xbfh + xb, (const char*)g_Xbfl + xb,
                               (const char*)g_XTh + tb,  (const char*)g_XTl + tb};
#pragma unroll
        for (int a = 0; a < 4; a++) {
            int q = tid;
            uint32_t dst;
            const char* src;
            if (a < 2) {
                int j = q >> 1, c = q & 1;
                dst = (uint32_t)(j * 32 + ((c ^ ((j >> 2) & 1)) << 4));
                src = srcs[a] + (size_t)j * 32 + c * 16;
            } else {
                int t = q >> 4, c = q & 15;
                dst = (uint32_t)(t * 256 + ((c ^ t) << 4));
                src = srcs[a] + (size_t)t * 2048 + c * 16;
            }
            cp_async16(smem_u32(&sb[st][a][0]) + dst, src);
        }
        cp_commit();
    };

    __syncthreads();            // sInj ready
    stage(0, 0);

    for (int jt = 0; jt < 8; jt++) {
        cp_wait<0>();
        __syncthreads();
        if (jt < 7) stage((jt + 1) & 1, jt + 1);

        const uint32_t sbase = smem_u32(&sb[jt & 1][0][0]);

#pragma unroll 2
        for (int s2 = 0; s2 < 8; s2++) {
            const int js = s2 * 16;
            const int jabs = jt * 128 + js;
            const int jstep = jt * 8 + s2;

            // --- shared B-frags: S (Xj) and PV (XT) ---
            uint32_t bh4[4], bl4[4];
            ldsm_x4(bh4, sbase + js * 32 + offS);
            ldsm_x4(bl4, sbase + 4096 + js * 32 + offS);
            const uint32_t cj = 2 * s2 + cbit;
            const uint32_t offP = (uint32_t)(tl * 256 + ((cj ^ tl) << 4));
            uint32_t th4[4], tl4[4];
            ldsm_x4(th4, sbase + 2 * 4096 + offP);
            ldsm_x4(tl4, sbase + 3 * 4096 + offP);

            float2 nj0 = *(const float2*)&sInj[jabs + 2 * tg];
            float2 nj1 = *(const float2*)&sInj[jabs + 8 + 2 * tg];

#pragma unroll
            for (int p = 0; p < 2; p++) {
                // coalesced beta fragments
                const float4* bp =
                    g_bperm + (((size_t)(ib0 + p) * 64 + jstep) * 32 + lane) * 2;
                float4 v0 = bp[0];   // rows g:    {j0,j0+1, j8,j8+1}
                float4 v1 = bp[1];   // rows 8+g

                float s0[4] = {0.f, 0.f, 0.f, 0.f};
                float s1[4] = {0.f, 0.f, 0.f, 0.f};
                mma16816(s0, aih[p], &bh4[0]); mma16816(s0, aih[p], &bl4[0]);
                mma16816(s0, ail[p], &bh4[0]);
                mma16816(s1, aih[p], &bh4[2]); mma16816(s1, aih[p], &bl4[2]);
                mma16816(s1, ail[p], &bh4[2]);

                float p00 = sig_tanh(v0.x * s0[0] * nia[p] * nj0.x);
                float p01 = sig_tanh(v0.y * s0[1] * nia[p] * nj0.y);
                float p02 = sig_tanh(v1.x * s0[2] * nib[p] * nj0.x);
                float p03 = sig_tanh(v1.y * s0[3] * nib[p] * nj0.y);
                float p10 = sig_tanh(v0.z * s1[0] * nia[p] * nj1.x);
                float p11 = sig_tanh(v0.w * s1[1] * nia[p] * nj1.y);
                float p12 = sig_tanh(v1.z * s1[2] * nib[p] * nj1.x);
                float p13 = sig_tanh(v1.w * s1[3] * nib[p] * nj1.y);

                uint32_t pah[4], pal[4];
                pah[0] = pack_bf16x2(p01, p00);
                pah[1] = pack_bf16x2(p03, p02);
                pah[2] = pack_bf16x2(p11, p10);
                pah[3] = pack_bf16x2(p13, p12);
                pal[0] = pack_bf16x2(p01 - bf16hi_f(pah[0]), p00 - bf16lo_f(pah[0]));
                pal[1] = pack_bf16x2(p03 - bf16hi_f(pah[1]), p02 - bf16lo_f(pah[1]));
                pal[2] = pack_bf16x2(p11 - bf16hi_f(pah[2]), p10 - bf16lo_f(pah[2]));
                pal[3] = pack_bf16x2(p13 - bf16hi_f(pah[3]), p12 - bf16lo_f(pah[3]));

                mma16816(o[p][0], pah, &th4[0]); mma16816(o[p][0], pah, &tl4[0]);
                mma16816(o[p][0], pal, &th4[0]);
                mma16816(o[p][1], pah, &th4[2]); mma16816(o[p][1], pah, &tl4[2]);
                mma16816(o[p][1], pal, &th4[2]);
            }
        }
    }

    // epilogue: per pair, O (16i x 16t) -> g_cos[b][i][t][ch]
#pragma unroll
    for (int p = 0; p < 2; p++) {
        const int r = rw + 16 * p + g;
        float* base = g_cos + (((size_t)(b * 1024 + r) * 16) * 16) + ch;
        base[(2 * tg) * 16]            = o[p][0][0];
        base[(2 * tg + 1) * 16]        = o[p][0][1];
        base[2048 + (2 * tg) * 16]     = o[p][0][2];
        base[2048 + (2 * tg + 1) * 16] = o[p][0][3];
        base[(8 + 2 * tg) * 16]            = o[p][1][0];
        base[(8 + 2 * tg + 1) * 16]        = o[p][1][1];
        base[2048 + (8 + 2 * tg) * 16]     = o[p][1][2];
        base[2048 + (8 + 2 * tg + 1) * 16] = o[p][1][3];
    }
}

// =============================================================================
// K4: fuse + channel softmax
// =============================================================================
__global__ __launch_bounds__(256) void k4_final(const float* __restrict__ x,
                                                float* __restrict__ out)
{
    const int idx = blockIdx.x * 256 + threadIdx.x;
    const int t = idx & 15;
    const int i = (idx >> 4) & 1023;
    const int b = idx >> 14;

    const float* gc = g_gc + (size_t)idx * 16;
    const float* cs = g_cos + (size_t)idx * 16;

    float g[16];
#pragma unroll
    for (int c = 0; c < 16; c++) {
        float xv = x[(((b << 4) + c) << 14) + (i << 4) + t];
        float r = gc[c] + xv;
        r = r > 0.f ? r : 0.f;
        g[c] = cs[c] * r;
    }
    float m = g[0];
#pragma unroll
    for (int c = 1; c < 16; c++) m = fmaxf(m, g[c]);
    float s = 0.f;
#pragma unroll
    for (int c = 0; c < 16; c++) {
        float e = __expf(g[c] - m);
        g[c] = e;
        s += e;
    }
    float rs = __fdividef(1.f, s);
#pragma unroll
    for (int c = 0; c < 16; c++)
        out[(((b << 4) + c) << 14) + (i << 4) + t] = g[c] * rs;
}

// =============================================================================
extern "C" void kernel_launch(void* const* d_in, const int* in_sizes, int n_in,
                              void* d_out, int out_size)
{
    const float* x     = (const float*)d_in[0];
    const float* beta  = (const float*)d_in[1];
    const float* theta = (const float*)d_in[2];
    const float* bias  = (const float*)d_in[3];
    const float* Lk    = (const float*)d_in[4];
    float* out = (float*)d_out;

    p1_convA<<<64, 256>>>(x);
    p2_convB<<<dim3(64, 32), 256>>>(Lk);
    p3_permBeta<<<512, 256>>>(beta);
    k1_mma<<<dim3(16, 8), 256>>>();
    k3t<<<dim3(4, 64), 256>>>();
    k2_fold<<<256, 256>>>(x, theta, bias);
    k4_final<<<256, 256>>>(x, out);
}